// round 4
// baseline (speedup 1.0000x reference)
#include <cuda_runtime.h>
#include <cstdint>

#define N_  64
#define C_  64
#define T_  128
#define V_  25
#define H_  3
#define O_  192

// ---------------- scratch ----------------
__device__ __align__(16) float g_pe[C_*V_];
__device__ __align__(16) float g_WqkvT[C_*O_];              // [c][o]
__device__ __align__(16) float g_Wt[960*64];                // [k][co]
__device__ __align__(16) float g_attpart[64*8*300*26];
__device__ __align__(16) float g_att[N_*H_*V_*V_];
__device__ __align__(16) float g_z[N_*C_*T_*V_];
__device__ __align__(16) float g_bnpart[4096*128];
__device__ __align__(16) float g_bn[128];

typedef unsigned long long ull;

// ---------------- f32x2 helpers ----------------
static __device__ __forceinline__ ull pack2(float a, float b){
  ull r;
  asm("mov.b64 %0, {%1, %2};" : "=l"(r) : "f"(a), "f"(b));
  return r;
}
static __device__ __forceinline__ void fma2(ull& d, ull a, ull b){
  asm("fma.rn.f32x2 %0, %1, %2, %0;" : "+l"(d) : "l"(a), "l"(b));
}
static __device__ __forceinline__ float lo2(ull v){ return __uint_as_float((unsigned)v); }
static __device__ __forceinline__ float hi2(ull v){ return __uint_as_float((unsigned)(v>>32)); }

// ---------------- init ----------------
__global__ void k_init(const float* __restrict__ Wqkv, const float* __restrict__ Wout) {
  const int stride = gridDim.x * blockDim.x;
  const int i0 = blockIdx.x * blockDim.x + threadIdx.x;
  for (int i = i0; i < C_*V_; i += stride) {
    int c = i / V_, v = i - (i / V_) * V_;
    int ii = c >> 1;
    float dv = __expf(-(2.0f * ii) * (logf(10000.0f) / 64.0f));
    float ang = (float)v * dv;
    g_pe[i] = (c & 1) ? cosf(ang) : sinf(ang);
  }
  for (int i = i0; i < C_*O_; i += stride) {
    int c = i / O_, o = i - (i / O_) * O_;
    g_WqkvT[i] = Wqkv[o * C_ + c];
  }
  for (int i = i0; i < 960*64; i += stride) {
    int k = i >> 6, co = i & 63;
    g_Wt[i] = Wout[co * 960 + k];
  }
}

// ---------------- kernel A: QK GEMM + Gram (round-2 verbatim, known good) ----------------
// grid (8 tc, 64 n), 384 threads, 2 CTAs/SM. smem 75776 B.
__global__ __launch_bounds__(384, 2) void k_qkatt(const float* __restrict__ x,
                                                  const float* __restrict__ bqkv) {
  extern __shared__ float sm[];
  float* sW  = sm;                 // [c][192]  12288
  float* sxs = sW + 12288;         // [c][26]   1664
  float* sqk = sxs + 1664;         // [o][26]   4992
  const int tid = threadIdx.x;
  const int n = blockIdx.y, tc = blockIdx.x;

  for (int i = tid; i < 12288; i += 384) sW[i] = g_WqkvT[i];
  if (tid < 64) sxs[tid*26 + 25] = 0.f;
  if (tid < 192) sqk[tid*26 + 25] = 0.f;

  // QK split: o = tid%192, part = tid/192 handles u-pair range
  const int o = tid % 192;
  const int part = tid / 192;
  const int j0 = part ? 7 : 0;
  const float bo = bqkv[o];

  // Gram: threads 0..299: row = tid>>2 (h*25+u), cq = tid&3 (c-quarter)
  const int grow = tid >> 2, gcq = tid & 3;
  const bool gact = (tid < 300);
  const int gh = grow / 25, gu = grow - (grow/25)*25;
  ull gacc[13];
  #pragma unroll
  for (int j = 0; j < 13; ++j) gacc[j] = 0ULL;

  const int tbeg = tc * 16;
  for (int t = tbeg; t < tbeg + 16; ++t) {
    __syncthreads();
    for (int i = tid; i < 1600; i += 384) {
      int c = i / 25, v = i - c*25;
      sxs[c*26 + v] = x[(((size_t)n*C_ + c)*T_ + t)*V_ + v] + g_pe[i];
    }
    __syncthreads();
    { // qk[o][u] for this part's u range
      ull a2[7];
      ull binit = pack2(bo, bo);
      #pragma unroll
      for (int jj = 0; jj < 7; ++jj) a2[jj] = binit;
      const float* wp = sW + o;
      #pragma unroll 4
      for (int c = 0; c < 64; ++c) {
        float w = wp[c*192];
        ull w2 = pack2(w, w);
        const ull* xr = (const ull*)(sxs + c*26) + j0;
        #pragma unroll
        for (int jj = 0; jj < 7; ++jj) fma2(a2[jj], w2, xr[jj]);
      }
      float* q = sqk + o*26;
      if (part == 0) {
        #pragma unroll
        for (int jj = 0; jj < 7; ++jj) { q[2*jj] = lo2(a2[jj]); q[2*jj+1] = hi2(a2[jj]); }
      } else {
        #pragma unroll
        for (int jj = 0; jj < 5; ++jj) {
          q[14+2*jj] = lo2(a2[jj]); q[15+2*jj] = hi2(a2[jj]);
        }
        q[24] = lo2(a2[5]);   // col 25 stays 0
      }
    }
    __syncthreads();
    if (gact) {
      #pragma unroll
      for (int c8 = 0; c8 < 8; ++c8) {
        int c = gcq*8 + c8;
        float qv = sqk[(gh*32 + c)*26 + gu];
        ull q2 = pack2(qv, qv);
        const ull* kp = (const ull*)(sqk + (96 + gh*32 + c)*26);
        #pragma unroll
        for (int j = 0; j < 13; ++j) fma2(gacc[j], q2, kp[j]);
      }
    }
  }
  if (gact) {
    ull* op = (ull*)(g_attpart + ((size_t)(n*8 + tc)*300 + tid)*26);
    #pragma unroll
    for (int j = 0; j < 13; ++j) op[j] = gacc[j];
  }
}

// ---------------- kernel A2 ----------------
__global__ void k_att2(const float* __restrict__ alphas, const float* __restrict__ att0s) {
  int i = blockIdx.x * blockDim.x + threadIdx.x;
  if (i >= N_*1875) return;
  int n = i / 1875, r = i - n*1875;
  int h = r / 625, rr = r - h*625;
  int u = rr / 25, v = rr - (rr/25)*25;
  int row = h*25 + u;
  float s = 0.f;
  #pragma unroll
  for (int tc = 0; tc < 8; ++tc)
    #pragma unroll
    for (int cq = 0; cq < 4; ++cq)
      s += g_attpart[((size_t)(n*8 + tc)*300 + row*4 + cq)*26 + v];
  g_att[i] = tanhf(s * (1.0f/4096.0f)) * alphas[h] + att0s[r];
}

// ---------------- kernel B: att-apply + conv + BN partials ----------------
// grid (16 tc, 64 n), 1024 threads.
// smem floats: ypad 192*241=46272 | satt 75*28=2100 | sx 64*101=6464 | sWc 2560
__global__ __launch_bounds__(1024, 1) void k_main(const float* __restrict__ x,
                                                  const float* __restrict__ bout) {
  extern __shared__ float sm[];
  float* ypad = sm;                 // [ch=192][241]: t*30 + col, cols 0..28 used
  float* satt = ypad + 46272;       // [h*25+u][28]
  float* sx   = satt + 2100;        // [ci][101]: t4*25+v
  float* sWc  = sx + 6464;          // [kk=40][64]
  const int tid = threadIdx.x;
  const int tx = tid & 31;
  const int wid = tid >> 5;         // 0..31
  const int o8 = wid & 7;
  const int part = wid >> 3;        // 0..3
  const int n = blockIdx.y;
  const int t0 = blockIdx.x * 8;

  for (int i = tid; i < 1875; i += 1024) {
    int h = i / 625, r = i - h*625;
    int u = r / 25, v = r - (r/25)*25;
    satt[(h*25 + u)*28 + v] = g_att[(size_t)n*1875 + i];
  }
  for (int i = tid; i < 225; i += 1024) { int row = i/3, c = 25 + (i - (i/3)*3); satt[row*28 + c] = 0.f; }
  for (int i = tid; i < 6144; i += 1024) {
    int rt = i >> 2, p = i & 3;
    int ch = rt >> 3, t = rt & 7;
    int col = (p < 2) ? p : (p + 25);
    ypad[ch*241 + t*30 + col] = 0.f;
  }

  // Phase 1: two halves of 4 t each
  for (int half = 0; half < 2; ++half) {
    __syncthreads();
    const float* xg = x + (((size_t)n*C_)*T_ + t0 + half*4)*V_;
    for (int i = tid; i < 6400; i += 1024) {
      int ci = i / 100, r = i - ci*100;
      sx[ci*101 + r] = xg[(size_t)ci*3200 + r];
    }
    __syncthreads();
    if (tid < 768) {
      int grp = tid >> 6, ci = tid & 63;
      int h = grp >> 2, t4 = grp & 3;
      ull a2[13];
      #pragma unroll
      for (int j = 0; j < 13; ++j) a2[j] = 0ULL;
      const float* sxp = sx + ci*101 + t4*25;
      const float* ap0 = satt + h*25*28;
      #pragma unroll
      for (int u = 0; u < 25; ++u) {
        float xv = sxp[u];
        ull xp = pack2(xv, xv);
        const ull* ar = (const ull*)(ap0 + u*28);
        #pragma unroll
        for (int j = 0; j < 13; ++j) fma2(a2[j], xp, ar[j]);
      }
      float* yr = ypad + (h*64 + ci)*241 + (half*4 + t4)*30 + 2;
      #pragma unroll
      for (int j = 0; j < 12; ++j) { yr[2*j] = lo2(a2[j]); yr[2*j+1] = hi2(a2[j]); }
      yr[24] = lo2(a2[12]);
    }
  }

  // Phase 2: conv GEMM
  const int tvA = tx + 32*part;            // always < 200
  const int tvB = tx + 32*(part + 4);
  const bool vB = (tvB < 200);
  const int tvBc = vB ? tvB : 199;
  const int offA = (tvA/25)*30 + (tvA - (tvA/25)*25);
  const int offB = (tvBc/25)*30 + (tvBc - (tvBc/25)*25);

  ull aA[4], aB[4];
  #pragma unroll
  for (int j = 0; j < 4; ++j) { aA[j] = 0ULL; aB[j] = 0ULL; }

  for (int k0 = 0; k0 < 960; k0 += 40) {
    __syncthreads();
    for (int i = tid; i < 2560; i += 1024) sWc[i] = g_Wt[k0*64 + i];
    __syncthreads();
    const int ch0 = k0 / 5;
    #pragma unroll
    for (int cc = 0; cc < 8; ++cc) {
      const float* yb = ypad + (ch0 + cc)*241;
      const float* wb = sWc + cc*320 + o8*8;
      #pragma unroll
      for (int dv = 0; dv < 5; ++dv) {
        ull w0 = *(const ull*)(wb + dv*64);
        ull w1 = *(const ull*)(wb + dv*64 + 2);
        ull w2 = *(const ull*)(wb + dv*64 + 4);
        ull w3 = *(const ull*)(wb + dv*64 + 6);
        float yA = yb[offA + dv];
        float yB = yb[offB + dv];
        ull pA = pack2(yA, yA), pB = pack2(yB, yB);
        fma2(aA[0], w0, pA); fma2(aA[1], w1, pA);
        fma2(aA[2], w2, pA); fma2(aA[3], w3, pA);
        fma2(aB[0], w0, pB); fma2(aB[1], w1, pB);
        fma2(aB[2], w2, pB); fma2(aB[3], w3, pB);
      }
    }
  }

  // Epilogue: store z + BN partials
  float bsum[8], bsq[8];
  const size_t zbase = (size_t)n*204800 + (size_t)t0*25;
  #pragma unroll
  for (int j = 0; j < 4; ++j) {
    int co0 = o8*8 + 2*j;
    float b0 = bout[co0], b1 = bout[co0 + 1];
    float s0 = 0.f, q0 = 0.f, s1 = 0.f, q1 = 0.f;
    {
      float z0 = lo2(aA[j]) + b0;
      float z1 = hi2(aA[j]) + b1;
      g_z[zbase + (size_t)co0*3200 + tvA]       = z0;
      g_z[zbase + (size_t)(co0+1)*3200 + tvA]   = z1;
      s0 += z0; q0 += z0*z0; s1 += z1; q1 += z1*z1;
    }
    if (vB) {
      float z0 = lo2(aB[j]) + b0;
      float z1 = hi2(aB[j]) + b1;
      g_z[zbase + (size_t)co0*3200 + tvB]       = z0;
      g_z[zbase + (size_t)(co0+1)*3200 + tvB]   = z1;
      s0 += z0; q0 += z0*z0; s1 += z1; q1 += z1*z1;
    }
    bsum[2*j] = s0; bsq[2*j] = q0; bsum[2*j+1] = s1; bsq[2*j+1] = q1;
  }

  #pragma unroll
  for (int off = 16; off > 0; off >>= 1) {
    #pragma unroll
    for (int j = 0; j < 8; ++j) {
      bsum[j] += __shfl_down_sync(0xffffffffu, bsum[j], off);
      bsq[j]  += __shfl_down_sync(0xffffffffu, bsq[j],  off);
    }
  }
  if (tx == 0) {
    float* bp = g_bnpart + (((size_t)blockIdx.y*16 + blockIdx.x)*4 + part)*128;
    #pragma unroll
    for (int j = 0; j < 8; ++j) {
      bp[o8*8 + j]      = bsum[j];
      bp[64 + o8*8 + j] = bsq[j];
    }
  }
}

// ---------------- kernel C: BN reduce ----------------
__global__ void k_bnred(const float* __restrict__ gamma, const float* __restrict__ beta) {
  __shared__ float s[4][128];
  __shared__ float tot[128];
  const int tid = threadIdx.x;           // 512
  const int slot = tid & 127, part = tid >> 7;
  float sum = 0.f;
  for (int b = part; b < 4096; b += 4) sum += g_bnpart[(size_t)b*128 + slot];
  s[part][slot] = sum;
  __syncthreads();
  if (tid < 128) tot[tid] = s[0][tid] + s[1][tid] + s[2][tid] + s[3][tid];
  __syncthreads();
  if (tid < 64) {
    const float inv = 1.0f / 204800.0f;
    float mean = tot[tid] * inv;
    float var  = tot[64 + tid] * inv - mean*mean;
    float a = gamma[tid] * rsqrtf(var + 1e-5f);
    g_bn[tid]      = a;
    g_bn[64 + tid] = beta[tid] - mean * a;
  }
}

// ---------------- kernel D: epilogue ----------------
__global__ void k_out(const float* __restrict__ x, float* __restrict__ out) {
  const float4* z4 = (const float4*)g_z;
  const float4* x4 = (const float4*)x;
  float4* o4 = (float4*)out;
  const int total = (N_*C_*T_*V_) / 4;
  for (int i = blockIdx.x*blockDim.x + threadIdx.x; i < total; i += gridDim.x*blockDim.x) {
    int c = (i / 800) & 63;
    float a = g_bn[c], b = g_bn[64 + c];
    float4 z = z4[i], xx = x4[i], r;
    float v;
    v = z.x*a + b + xx.x; r.x = fmaxf(v, 0.1f*v);
    v = z.y*a + b + xx.y; r.y = fmaxf(v, 0.1f*v);
    v = z.z*a + b + xx.z; r.z = fmaxf(v, 0.1f*v);
    v = z.w*a + b + xx.w; r.w = fmaxf(v, 0.1f*v);
    o4[i] = r;
  }
}

// ---------------- launch ----------------
extern "C" void kernel_launch(void* const* d_in, const int* in_sizes, int n_in,
                              void* d_out, int out_size) {
  const float* x      = (const float*)d_in[0];
  const float* Wqkv   = (const float*)d_in[1];
  const float* bqkv   = (const float*)d_in[2];
  const float* alphas = (const float*)d_in[3];
  const float* att0s  = (const float*)d_in[4];
  const float* Wout   = (const float*)d_in[5];
  const float* bout   = (const float*)d_in[6];
  const float* gamma  = (const float*)d_in[7];
  const float* beta   = (const float*)d_in[8];
  float* out = (float*)d_out;

  cudaFuncSetAttribute(k_qkatt, cudaFuncAttributeMaxDynamicSharedMemorySize, 75776);
  cudaFuncSetAttribute(k_main,  cudaFuncAttributeMaxDynamicSharedMemorySize, 229584);

  k_init<<<64, 256>>>(Wqkv, Wout);
  k_qkatt<<<dim3(8, 64), 384, 75776>>>(x, bqkv);
  k_att2<<<(N_*1875 + 255)/256, 256>>>(alphas, att0s);
  k_main<<<dim3(16, 64), 1024, 229584>>>(x, bout);
  k_bnred<<<1, 512>>>(gamma, beta);
  k_out<<<4096, 256>>>(x, out);
}

// round 5
// speedup vs baseline: 1.1040x; 1.1040x over previous
#include <cuda_runtime.h>
#include <cstdint>

#define N_  64
#define C_  64
#define T_  128
#define V_  25
#define H_  3
#define O_  192

// ---------------- scratch ----------------
__device__ __align__(16) float g_pe[C_*V_];
__device__ __align__(16) float g_WqkvT[C_*O_];              // [c][o]
__device__ __align__(16) float g_Wt[960*64];                // [k][co]
__device__ __align__(16) float g_attpart[64*8*300*26];
__device__ __align__(16) float g_att[N_*H_*V_*V_];
__device__ __align__(16) float g_z[N_*C_*T_*V_];
__device__ __align__(16) float g_bnpart[3072*128];
__device__ __align__(16) float g_bn[128];

typedef unsigned long long ull;

// ---------------- f32x2 helpers ----------------
static __device__ __forceinline__ ull pack2(float a, float b){
  ull r;
  asm("mov.b64 %0, {%1, %2};" : "=l"(r) : "f"(a), "f"(b));
  return r;
}
static __device__ __forceinline__ void fma2(ull& d, ull a, ull b){
  asm("fma.rn.f32x2 %0, %1, %2, %0;" : "+l"(d) : "l"(a), "l"(b));
}
static __device__ __forceinline__ float lo2(ull v){ return __uint_as_float((unsigned)v); }
static __device__ __forceinline__ float hi2(ull v){ return __uint_as_float((unsigned)(v>>32)); }

// ---------------- init ----------------
__global__ void k_init(const float* __restrict__ Wqkv, const float* __restrict__ Wout) {
  const int stride = gridDim.x * blockDim.x;
  const int i0 = blockIdx.x * blockDim.x + threadIdx.x;
  for (int i = i0; i < C_*V_; i += stride) {
    int c = i / V_, v = i - (i / V_) * V_;
    int ii = c >> 1;
    float dv = __expf(-(2.0f * ii) * (logf(10000.0f) / 64.0f));
    float ang = (float)v * dv;
    g_pe[i] = (c & 1) ? cosf(ang) : sinf(ang);
  }
  for (int i = i0; i < C_*O_; i += stride) {
    int c = i / O_, o = i - (i / O_) * O_;
    g_WqkvT[i] = Wqkv[o * C_ + c];
  }
  for (int i = i0; i < 960*64; i += stride) {
    int k = i >> 6, co = i & 63;
    g_Wt[i] = Wout[co * 960 + k];
  }
}

// ---------------- kernel A: QK GEMM + Gram (round-2 verbatim, known good) ----------------
__global__ __launch_bounds__(384, 2) void k_qkatt(const float* __restrict__ x,
                                                  const float* __restrict__ bqkv) {
  extern __shared__ float sm[];
  float* sW  = sm;                 // [c][192]  12288
  float* sxs = sW + 12288;         // [c][26]   1664
  float* sqk = sxs + 1664;         // [o][26]   4992
  const int tid = threadIdx.x;
  const int n = blockIdx.y, tc = blockIdx.x;

  for (int i = tid; i < 12288; i += 384) sW[i] = g_WqkvT[i];
  if (tid < 64) sxs[tid*26 + 25] = 0.f;
  if (tid < 192) sqk[tid*26 + 25] = 0.f;

  const int o = tid % 192;
  const int part = tid / 192;
  const int j0 = part ? 7 : 0;
  const float bo = bqkv[o];

  const int grow = tid >> 2, gcq = tid & 3;
  const bool gact = (tid < 300);
  const int gh = grow / 25, gu = grow - (grow/25)*25;
  ull gacc[13];
  #pragma unroll
  for (int j = 0; j < 13; ++j) gacc[j] = 0ULL;

  const int tbeg = tc * 16;
  for (int t = tbeg; t < tbeg + 16; ++t) {
    __syncthreads();
    for (int i = tid; i < 1600; i += 384) {
      int c = i / 25, v = i - c*25;
      sxs[c*26 + v] = x[(((size_t)n*C_ + c)*T_ + t)*V_ + v] + g_pe[i];
    }
    __syncthreads();
    {
      ull a2[7];
      ull binit = pack2(bo, bo);
      #pragma unroll
      for (int jj = 0; jj < 7; ++jj) a2[jj] = binit;
      const float* wp = sW + o;
      #pragma unroll 4
      for (int c = 0; c < 64; ++c) {
        float w = wp[c*192];
        ull w2 = pack2(w, w);
        const ull* xr = (const ull*)(sxs + c*26) + j0;
        #pragma unroll
        for (int jj = 0; jj < 7; ++jj) fma2(a2[jj], w2, xr[jj]);
      }
      float* q = sqk + o*26;
      if (part == 0) {
        #pragma unroll
        for (int jj = 0; jj < 7; ++jj) { q[2*jj] = lo2(a2[jj]); q[2*jj+1] = hi2(a2[jj]); }
      } else {
        #pragma unroll
        for (int jj = 0; jj < 5; ++jj) {
          q[14+2*jj] = lo2(a2[jj]); q[15+2*jj] = hi2(a2[jj]);
        }
        q[24] = lo2(a2[5]);
      }
    }
    __syncthreads();
    if (gact) {
      #pragma unroll
      for (int c8 = 0; c8 < 8; ++c8) {
        int c = gcq*8 + c8;
        float qv = sqk[(gh*32 + c)*26 + gu];
        ull q2 = pack2(qv, qv);
        const ull* kp = (const ull*)(sqk + (96 + gh*32 + c)*26);
        #pragma unroll
        for (int j = 0; j < 13; ++j) fma2(gacc[j], q2, kp[j]);
      }
    }
  }
  if (gact) {
    ull* op = (ull*)(g_attpart + ((size_t)(n*8 + tc)*300 + tid)*26);
    #pragma unroll
    for (int j = 0; j < 13; ++j) op[j] = gacc[j];
  }
}

// ---------------- kernel A2 ----------------
__global__ void k_att2(const float* __restrict__ alphas, const float* __restrict__ att0s) {
  int i = blockIdx.x * blockDim.x + threadIdx.x;
  if (i >= N_*1875) return;
  int n = i / 1875, r = i - n*1875;
  int h = r / 625, rr = r - h*625;
  int u = rr / 25, v = rr - (rr/25)*25;
  int row = h*25 + u;
  float s = 0.f;
  #pragma unroll
  for (int tc = 0; tc < 8; ++tc)
    #pragma unroll
    for (int cq = 0; cq < 4; ++cq)
      s += g_attpart[((size_t)(n*8 + tc)*300 + row*4 + cq)*26 + v];
  g_att[i] = tanhf(s * (1.0f/4096.0f)) * alphas[h] + att0s[r];
}

// ---------------- kernel B: att-apply + conv + BN partials ----------------
// grid (16 tc, 64 n), 512 threads.
// smem floats: ypad 192*241=46272 | satt 75*28=2100 | sx 64*101=6464 | sWc 2560
__global__ __launch_bounds__(512, 1) void k_main(const float* __restrict__ x,
                                                 const float* __restrict__ bout) {
  extern __shared__ float sm[];
  float* ypad = sm;                 // [ch=192][241]: t*30 + col
  float* satt = ypad + 46272;       // [h*25+u][28]
  float* sx   = satt + 2100;        // [ci][101]
  float* sWc  = sx + 6464;          // [kk=40][64]
  const int tid = threadIdx.x;
  const int tx = tid & 31;
  const int wid = tid >> 5;         // 0..15
  const int o8 = wid & 7;
  const int tq = wid >> 3;          // 0/1
  const int n = blockIdx.y;
  const int t0 = blockIdx.x * 8;

  for (int i = tid; i < 1875; i += 512) {
    int h = i / 625, r = i - h*625;
    int u = r / 25, v = r - (r/25)*25;
    satt[(h*25 + u)*28 + v] = g_att[(size_t)n*1875 + i];
  }
  for (int i = tid; i < 225; i += 512) { int row = i/3, c = 25 + (i - (i/3)*3); satt[row*28 + c] = 0.f; }
  for (int i = tid; i < 6144; i += 512) {
    int rt = i >> 2, p = i & 3;
    int ch = rt >> 3, t = rt & 7;
    int col = (p < 2) ? p : (p + 25);
    ypad[ch*241 + t*30 + col] = 0.f;
  }

  // Phase 1: two halves of 4 t each; 768 tasks per half over 512 threads
  for (int half = 0; half < 2; ++half) {
    __syncthreads();
    const float* xg = x + (((size_t)n*C_)*T_ + t0 + half*4)*V_;
    for (int i = tid; i < 6400; i += 512) {
      int ci = i / 100, r = i - ci*100;
      sx[ci*101 + r] = xg[(size_t)ci*3200 + r];
    }
    __syncthreads();
    #pragma unroll
    for (int rep = 0; rep < 2; ++rep) {
      int task = tid + 512*rep;
      if (rep == 1 && tid >= 256) break;
      int h = task >> 8, t4 = (task >> 6) & 3, ci = task & 63;
      ull a2[13];
      #pragma unroll
      for (int j = 0; j < 13; ++j) a2[j] = 0ULL;
      const float* sxp = sx + ci*101 + t4*25;
      const float* ap0 = satt + h*25*28;
      #pragma unroll
      for (int u = 0; u < 25; ++u) {
        float xv = sxp[u];
        ull xp = pack2(xv, xv);
        const ull* ar = (const ull*)(ap0 + u*28);
        #pragma unroll
        for (int j = 0; j < 13; ++j) fma2(a2[j], xp, ar[j]);
      }
      float* yr = ypad + (h*64 + ci)*241 + (half*4 + t4)*30 + 2;
      #pragma unroll
      for (int j = 0; j < 12; ++j) { yr[2*j] = lo2(a2[j]); yr[2*j+1] = hi2(a2[j]); }
      yr[24] = lo2(a2[12]);
    }
  }

  // Phase 2: conv GEMM. 3 uniform slots per thread (tv < 192) + scalar tail (tv 192..199)
  int off[3];
  #pragma unroll
  for (int s = 0; s < 3; ++s) {
    int tv = tx + 32*tq + 64*s;
    off[s] = (tv/25)*30 + (tv - (tv/25)*25);
  }
  const int tco = tid >> 3;            // tail output channel 0..63
  const int ttv = 192 + (tid & 7);     // tail tv
  const int toff = 7*30 + (17 + (tid & 7));
  float tacc = 0.f;

  ull acc[3][4];
  #pragma unroll
  for (int s = 0; s < 3; ++s)
    #pragma unroll
    for (int j = 0; j < 4; ++j) acc[s][j] = 0ULL;

  for (int k0 = 0; k0 < 960; k0 += 40) {
    __syncthreads();
    for (int i = tid; i < 2560; i += 512) sWc[i] = g_Wt[k0*64 + i];
    __syncthreads();
    const int ch0 = k0 / 5;
    #pragma unroll
    for (int cc = 0; cc < 8; ++cc) {
      const float* yb = ypad + (ch0 + cc)*241;
      const float* wb = sWc + cc*320 + o8*8;
      #pragma unroll
      for (int dv = 0; dv < 5; ++dv) {
        float4 wA = *(const float4*)(wb + dv*64);
        float4 wB = *(const float4*)(wb + dv*64 + 4);
        ull w0 = pack2(wA.x, wA.y), w1 = pack2(wA.z, wA.w);
        ull w2 = pack2(wB.x, wB.y), w3 = pack2(wB.z, wB.w);
        #pragma unroll
        for (int s = 0; s < 3; ++s) {
          float yv = yb[off[s] + dv];
          ull yp = pack2(yv, yv);
          fma2(acc[s][0], w0, yp); fma2(acc[s][1], w1, yp);
          fma2(acc[s][2], w2, yp); fma2(acc[s][3], w3, yp);
        }
      }
    }
    // tail: one scalar output per thread
    #pragma unroll
    for (int cc = 0; cc < 8; ++cc) {
      const float* yb = ypad + (ch0 + cc)*241 + toff;
      const float* wb = sWc + cc*320 + tco;
      #pragma unroll
      for (int dv = 0; dv < 5; ++dv) tacc += wb[dv*64] * yb[dv];
    }
  }

  // Epilogue: store z + BN partials
  const size_t zbase = (size_t)n*204800 + (size_t)t0*25;
  const int cta = blockIdx.y*16 + blockIdx.x;
  float bsum[8], bsq[8];
  #pragma unroll
  for (int j = 0; j < 4; ++j) {
    int co0 = o8*8 + 2*j;
    float b0 = bout[co0], b1 = bout[co0 + 1];
    float s0 = 0.f, q0 = 0.f, s1 = 0.f, q1 = 0.f;
    #pragma unroll
    for (int s = 0; s < 3; ++s) {
      int tv = tx + 32*tq + 64*s;
      float z0 = lo2(acc[s][j]) + b0;
      float z1 = hi2(acc[s][j]) + b1;
      g_z[zbase + (size_t)co0*3200 + tv]       = z0;
      g_z[zbase + (size_t)(co0+1)*3200 + tv]   = z1;
      s0 += z0; q0 += z0*z0; s1 += z1; q1 += z1*z1;
    }
    bsum[2*j] = s0; bsq[2*j] = q0; bsum[2*j+1] = s1; bsq[2*j+1] = q1;
  }

  #pragma unroll
  for (int off2 = 16; off2 > 0; off2 >>= 1) {
    #pragma unroll
    for (int j = 0; j < 8; ++j) {
      bsum[j] += __shfl_down_sync(0xffffffffu, bsum[j], off2);
      bsq[j]  += __shfl_down_sync(0xffffffffu, bsq[j],  off2);
    }
  }
  if (tx == 0) {
    float* bp = g_bnpart + ((size_t)cta*3 + tq)*128;
    #pragma unroll
    for (int j = 0; j < 8; ++j) {
      bp[o8*8 + j]      = bsum[j];
      bp[64 + o8*8 + j] = bsq[j];
    }
  }

  // tail store + tail BN partial (8-lane group reduce, deterministic)
  {
    float zt = tacc + bout[tco];
    g_z[zbase + (size_t)tco*3200 + ttv] = zt;
    float ts = zt, tq2 = zt*zt;
    #pragma unroll
    for (int d = 4; d > 0; d >>= 1) {
      ts  += __shfl_down_sync(0xffffffffu, ts,  d, 8);
      tq2 += __shfl_down_sync(0xffffffffu, tq2, d, 8);
    }
    if ((tid & 7) == 0) {
      float* bp = g_bnpart + ((size_t)cta*3 + 2)*128;
      bp[tco]      = ts;
      bp[64 + tco] = tq2;
    }
  }
}

// ---------------- kernel C: BN reduce ----------------
__global__ void k_bnred(const float* __restrict__ gamma, const float* __restrict__ beta) {
  __shared__ float s[4][128];
  __shared__ float tot[128];
  const int tid = threadIdx.x;           // 512
  const int slot = tid & 127, part = tid >> 7;
  float sum = 0.f;
  for (int b = part; b < 3072; b += 4) sum += g_bnpart[(size_t)b*128 + slot];
  s[part][slot] = sum;
  __syncthreads();
  if (tid < 128) tot[tid] = s[0][tid] + s[1][tid] + s[2][tid] + s[3][tid];
  __syncthreads();
  if (tid < 64) {
    const float inv = 1.0f / 204800.0f;
    float mean = tot[tid] * inv;
    float var  = tot[64 + tid] * inv - mean*mean;
    float a = gamma[tid] * rsqrtf(var + 1e-5f);
    g_bn[tid]      = a;
    g_bn[64 + tid] = beta[tid] - mean * a;
  }
}

// ---------------- kernel D: epilogue ----------------
__global__ void k_out(const float* __restrict__ x, float* __restrict__ out) {
  const float4* z4 = (const float4*)g_z;
  const float4* x4 = (const float4*)x;
  float4* o4 = (float4*)out;
  const int total = (N_*C_*T_*V_) / 4;
  for (int i = blockIdx.x*blockDim.x + threadIdx.x; i < total; i += gridDim.x*blockDim.x) {
    int c = (i / 800) & 63;
    float a = g_bn[c], b = g_bn[64 + c];
    float4 z = z4[i], xx = x4[i], r;
    float v;
    v = z.x*a + b + xx.x; r.x = fmaxf(v, 0.1f*v);
    v = z.y*a + b + xx.y; r.y = fmaxf(v, 0.1f*v);
    v = z.z*a + b + xx.z; r.z = fmaxf(v, 0.1f*v);
    v = z.w*a + b + xx.w; r.w = fmaxf(v, 0.1f*v);
    o4[i] = r;
  }
}

// ---------------- launch ----------------
extern "C" void kernel_launch(void* const* d_in, const int* in_sizes, int n_in,
                              void* d_out, int out_size) {
  const float* x      = (const float*)d_in[0];
  const float* Wqkv   = (const float*)d_in[1];
  const float* bqkv   = (const float*)d_in[2];
  const float* alphas = (const float*)d_in[3];
  const float* att0s  = (const float*)d_in[4];
  const float* Wout   = (const float*)d_in[5];
  const float* bout   = (const float*)d_in[6];
  const float* gamma  = (const float*)d_in[7];
  const float* beta   = (const float*)d_in[8];
  float* out = (float*)d_out;

  cudaFuncSetAttribute(k_qkatt, cudaFuncAttributeMaxDynamicSharedMemorySize, 75776);
  cudaFuncSetAttribute(k_main,  cudaFuncAttributeMaxDynamicSharedMemorySize, 229584);

  k_init<<<64, 256>>>(Wqkv, Wout);
  k_qkatt<<<dim3(8, 64), 384, 75776>>>(x, bqkv);
  k_att2<<<(N_*1875 + 255)/256, 256>>>(alphas, att0s);
  k_main<<<dim3(16, 64), 512, 229584>>>(x, bout);
  k_bnred<<<1, 512>>>(gamma, beta);
  k_out<<<4096, 256>>>(x, out);
}

// round 6
// speedup vs baseline: 1.1053x; 1.0012x over previous
#include <cuda_runtime.h>
#include <cstdint>

#define N_  64
#define C_  64
#define T_  128
#define V_  25
#define H_  3
#define O_  192

// ---------------- scratch ----------------
__device__ __align__(16) float g_pe[C_*V_];
__device__ __align__(16) float g_WqkvT[C_*O_];              // [c][o]
__device__ __align__(16) float g_Wt[960*64];                // [k][co]
__device__ __align__(16) float g_attpart[64*8*300*26];
__device__ __align__(16) float g_att[N_*H_*V_*V_];
__device__ __align__(16) float g_z[N_*C_*T_*V_];
__device__ __align__(16) float g_bnpart[3072*128];
__device__ __align__(16) float g_bn[128];

typedef unsigned long long ull;

// ---------------- f32x2 helpers ----------------
static __device__ __forceinline__ ull pack2(float a, float b){
  ull r;
  asm("mov.b64 %0, {%1, %2};" : "=l"(r) : "f"(a), "f"(b));
  return r;
}
static __device__ __forceinline__ void fma2(ull& d, ull a, ull b){
  asm("fma.rn.f32x2 %0, %1, %2, %0;" : "+l"(d) : "l"(a), "l"(b));
}
static __device__ __forceinline__ float lo2(ull v){ return __uint_as_float((unsigned)v); }
static __device__ __forceinline__ float hi2(ull v){ return __uint_as_float((unsigned)(v>>32)); }

// ---------------- init ----------------
__global__ void k_init(const float* __restrict__ Wqkv, const float* __restrict__ Wout) {
  const int stride = gridDim.x * blockDim.x;
  const int i0 = blockIdx.x * blockDim.x + threadIdx.x;
  for (int i = i0; i < C_*V_; i += stride) {
    int c = i / V_, v = i - (i / V_) * V_;
    int ii = c >> 1;
    float dv = __expf(-(2.0f * ii) * (logf(10000.0f) / 64.0f));
    float ang = (float)v * dv;
    g_pe[i] = (c & 1) ? cosf(ang) : sinf(ang);
  }
  for (int i = i0; i < C_*O_; i += stride) {
    int c = i / O_, o = i - (i / O_) * O_;
    g_WqkvT[i] = Wqkv[o * C_ + c];
  }
  for (int i = i0; i < 960*64; i += stride) {
    int k = i >> 6, co = i & 63;
    g_Wt[i] = Wout[co * 960 + k];
  }
}

// ---------------- kernel A: QK GEMM + Gram (round-2 verbatim, known good) ----------------
__global__ __launch_bounds__(384, 2) void k_qkatt(const float* __restrict__ x,
                                                  const float* __restrict__ bqkv) {
  extern __shared__ float sm[];
  float* sW  = sm;                 // [c][192]  12288
  float* sxs = sW + 12288;         // [c][26]   1664
  float* sqk = sxs + 1664;         // [o][26]   4992
  const int tid = threadIdx.x;
  const int n = blockIdx.y, tc = blockIdx.x;

  for (int i = tid; i < 12288; i += 384) sW[i] = g_WqkvT[i];
  if (tid < 64) sxs[tid*26 + 25] = 0.f;
  if (tid < 192) sqk[tid*26 + 25] = 0.f;

  const int o = tid % 192;
  const int part = tid / 192;
  const int j0 = part ? 7 : 0;
  const float bo = bqkv[o];

  const int grow = tid >> 2, gcq = tid & 3;
  const bool gact = (tid < 300);
  const int gh = grow / 25, gu = grow - (grow/25)*25;
  ull gacc[13];
  #pragma unroll
  for (int j = 0; j < 13; ++j) gacc[j] = 0ULL;

  const int tbeg = tc * 16;
  for (int t = tbeg; t < tbeg + 16; ++t) {
    __syncthreads();
    for (int i = tid; i < 1600; i += 384) {
      int c = i / 25, v = i - c*25;
      sxs[c*26 + v] = x[(((size_t)n*C_ + c)*T_ + t)*V_ + v] + g_pe[i];
    }
    __syncthreads();
    {
      ull a2[7];
      ull binit = pack2(bo, bo);
      #pragma unroll
      for (int jj = 0; jj < 7; ++jj) a2[jj] = binit;
      const float* wp = sW + o;
      #pragma unroll 4
      for (int c = 0; c < 64; ++c) {
        float w = wp[c*192];
        ull w2 = pack2(w, w);
        const ull* xr = (const ull*)(sxs + c*26) + j0;
        #pragma unroll
        for (int jj = 0; jj < 7; ++jj) fma2(a2[jj], w2, xr[jj]);
      }
      float* q = sqk + o*26;
      if (part == 0) {
        #pragma unroll
        for (int jj = 0; jj < 7; ++jj) { q[2*jj] = lo2(a2[jj]); q[2*jj+1] = hi2(a2[jj]); }
      } else {
        #pragma unroll
        for (int jj = 0; jj < 5; ++jj) {
          q[14+2*jj] = lo2(a2[jj]); q[15+2*jj] = hi2(a2[jj]);
        }
        q[24] = lo2(a2[5]);
      }
    }
    __syncthreads();
    if (gact) {
      #pragma unroll
      for (int c8 = 0; c8 < 8; ++c8) {
        int c = gcq*8 + c8;
        float qv = sqk[(gh*32 + c)*26 + gu];
        ull q2 = pack2(qv, qv);
        const ull* kp = (const ull*)(sqk + (96 + gh*32 + c)*26);
        #pragma unroll
        for (int j = 0; j < 13; ++j) fma2(gacc[j], q2, kp[j]);
      }
    }
  }
  if (gact) {
    ull* op = (ull*)(g_attpart + ((size_t)(n*8 + tc)*300 + tid)*26);
    #pragma unroll
    for (int j = 0; j < 13; ++j) op[j] = gacc[j];
  }
}

// ---------------- kernel A2 ----------------
__global__ void k_att2(const float* __restrict__ alphas, const float* __restrict__ att0s) {
  int i = blockIdx.x * blockDim.x + threadIdx.x;
  if (i >= N_*1875) return;
  int n = i / 1875, r = i - n*1875;
  int h = r / 625, rr = r - h*625;
  int u = rr / 25, v = rr - (rr/25)*25;
  int row = h*25 + u;
  float s = 0.f;
  #pragma unroll
  for (int tc = 0; tc < 8; ++tc)
    #pragma unroll
    for (int cq = 0; cq < 4; ++cq)
      s += g_attpart[((size_t)(n*8 + tc)*300 + row*4 + cq)*26 + v];
  g_att[i] = tanhf(s * (1.0f/4096.0f)) * alphas[h] + att0s[r];
}

// ---------------- kernel B: att-apply + conv + BN partials ----------------
// grid (16 tc, 64 n), 512 threads.
// smem floats: ypad 192*241=46272 | satt 75*28=2100 | sx 64*101=6464 | sWc 2560
__global__ __launch_bounds__(512, 1) void k_main(const float* __restrict__ x,
                                                 const float* __restrict__ bout) {
  extern __shared__ float sm[];
  float* ypad = sm;                 // [ch=192][241]: t*30 + col
  float* satt = ypad + 46272;       // [h*25+u][28]
  float* sx   = satt + 2100;        // [ci][101]
  float* sWc  = sx + 6464;          // [kk=40][64]
  const int tid = threadIdx.x;
  const int tx = tid & 31;
  const int wid = tid >> 5;         // 0..15
  const int o8 = wid & 7;
  const int tq = wid >> 3;          // 0/1
  const int n = blockIdx.y;
  const int t0 = blockIdx.x * 8;

  for (int i = tid; i < 1875; i += 512) {
    int h = i / 625, r = i - h*625;
    int u = r / 25, v = r - (r/25)*25;
    satt[(h*25 + u)*28 + v] = g_att[(size_t)n*1875 + i];
  }
  for (int i = tid; i < 225; i += 512) { int row = i/3, c = 25 + (i - (i/3)*3); satt[row*28 + c] = 0.f; }
  for (int i = tid; i < 6144; i += 512) {
    int rt = i >> 2, p = i & 3;
    int ch = rt >> 3, t = rt & 7;
    int col = (p < 2) ? p : (p + 25);
    ypad[ch*241 + t*30 + col] = 0.f;
  }

  // Phase 1: two halves of 4 t each; 768 tasks per half over 512 threads
  for (int half = 0; half < 2; ++half) {
    __syncthreads();
    const float* xg = x + (((size_t)n*C_)*T_ + t0 + half*4)*V_;
    for (int i = tid; i < 6400; i += 512) {
      int ci = i / 100, r = i - ci*100;
      sx[ci*101 + r] = xg[(size_t)ci*3200 + r];
    }
    __syncthreads();
    #pragma unroll
    for (int rep = 0; rep < 2; ++rep) {
      int task = tid + 512*rep;
      if (rep == 1 && tid >= 256) break;
      int h = task >> 8, t4 = (task >> 6) & 3, ci = task & 63;
      ull a2[13];
      #pragma unroll
      for (int j = 0; j < 13; ++j) a2[j] = 0ULL;
      const float* sxp = sx + ci*101 + t4*25;
      const float* ap0 = satt + h*25*28;
      #pragma unroll
      for (int u = 0; u < 25; ++u) {
        float xv = sxp[u];
        ull xp = pack2(xv, xv);
        const ull* ar = (const ull*)(ap0 + u*28);
        #pragma unroll
        for (int j = 0; j < 13; ++j) fma2(a2[j], xp, ar[j]);
      }
      float* yr = ypad + (h*64 + ci)*241 + (half*4 + t4)*30 + 2;
      #pragma unroll
      for (int j = 0; j < 12; ++j) { yr[2*j] = lo2(a2[j]); yr[2*j+1] = hi2(a2[j]); }
      yr[24] = lo2(a2[12]);
    }
  }

  // Phase 2: conv GEMM. 3 uniform slots per thread (tv < 192) + scalar tail (tv 192..199)
  int off[3];
  #pragma unroll
  for (int s = 0; s < 3; ++s) {
    int tv = tx + 32*tq + 64*s;
    off[s] = (tv/25)*30 + (tv - (tv/25)*25);
  }
  const int tco = tid >> 3;            // tail output channel 0..63
  const int ttv = 192 + (tid & 7);     // tail tv
  const int toff = 7*30 + (17 + (tid & 7));
  float tacc = 0.f;

  ull acc[3][4];
  #pragma unroll
  for (int s = 0; s < 3; ++s)
    #pragma unroll
    for (int j = 0; j < 4; ++j) acc[s][j] = 0ULL;

  for (int k0 = 0; k0 < 960; k0 += 40) {
    __syncthreads();
    for (int i = tid; i < 2560; i += 512) sWc[i] = g_Wt[k0*64 + i];
    __syncthreads();
    const int ch0 = k0 / 5;
    #pragma unroll
    for (int cc = 0; cc < 8; ++cc) {
      const float* yb = ypad + (ch0 + cc)*241;
      const float* wb = sWc + cc*320 + o8*8;
      #pragma unroll
      for (int dv = 0; dv < 5; ++dv) {
        float4 wA = *(const float4*)(wb + dv*64);
        float4 wB = *(const float4*)(wb + dv*64 + 4);
        ull w0 = pack2(wA.x, wA.y), w1 = pack2(wA.z, wA.w);
        ull w2 = pack2(wB.x, wB.y), w3 = pack2(wB.z, wB.w);
        #pragma unroll
        for (int s = 0; s < 3; ++s) {
          float yv = yb[off[s] + dv];
          ull yp = pack2(yv, yv);
          fma2(acc[s][0], w0, yp); fma2(acc[s][1], w1, yp);
          fma2(acc[s][2], w2, yp); fma2(acc[s][3], w3, yp);
        }
      }
    }
    // tail: one scalar output per thread
    #pragma unroll
    for (int cc = 0; cc < 8; ++cc) {
      const float* yb = ypad + (ch0 + cc)*241 + toff;
      const float* wb = sWc + cc*320 + tco;
      #pragma unroll
      for (int dv = 0; dv < 5; ++dv) tacc += wb[dv*64] * yb[dv];
    }
  }

  // Epilogue: store z + BN partials
  const size_t zbase = (size_t)n*204800 + (size_t)t0*25;
  const int cta = blockIdx.y*16 + blockIdx.x;
  float bsum[8], bsq[8];
  #pragma unroll
  for (int j = 0; j < 4; ++j) {
    int co0 = o8*8 + 2*j;
    float b0 = bout[co0], b1 = bout[co0 + 1];
    float s0 = 0.f, q0 = 0.f, s1 = 0.f, q1 = 0.f;
    #pragma unroll
    for (int s = 0; s < 3; ++s) {
      int tv = tx + 32*tq + 64*s;
      float z0 = lo2(acc[s][j]) + b0;
      float z1 = hi2(acc[s][j]) + b1;
      g_z[zbase + (size_t)co0*3200 + tv]       = z0;
      g_z[zbase + (size_t)(co0+1)*3200 + tv]   = z1;
      s0 += z0; q0 += z0*z0; s1 += z1; q1 += z1*z1;
    }
    bsum[2*j] = s0; bsq[2*j] = q0; bsum[2*j+1] = s1; bsq[2*j+1] = q1;
  }

  #pragma unroll
  for (int off2 = 16; off2 > 0; off2 >>= 1) {
    #pragma unroll
    for (int j = 0; j < 8; ++j) {
      bsum[j] += __shfl_down_sync(0xffffffffu, bsum[j], off2);
      bsq[j]  += __shfl_down_sync(0xffffffffu, bsq[j],  off2);
    }
  }
  if (tx == 0) {
    float* bp = g_bnpart + ((size_t)cta*3 + tq)*128;
    #pragma unroll
    for (int j = 0; j < 8; ++j) {
      bp[o8*8 + j]      = bsum[j];
      bp[64 + o8*8 + j] = bsq[j];
    }
  }

  // tail store + tail BN partial (8-lane group reduce, deterministic)
  {
    float zt = tacc + bout[tco];
    g_z[zbase + (size_t)tco*3200 + ttv] = zt;
    float ts = zt, tq2 = zt*zt;
    #pragma unroll
    for (int d = 4; d > 0; d >>= 1) {
      ts  += __shfl_down_sync(0xffffffffu, ts,  d, 8);
      tq2 += __shfl_down_sync(0xffffffffu, tq2, d, 8);
    }
    if ((tid & 7) == 0) {
      float* bp = g_bnpart + ((size_t)cta*3 + 2)*128;
      bp[tco]      = ts;
      bp[64 + tco] = tq2;
    }
  }
}

// ---------------- kernel C: BN reduce ----------------
__global__ void k_bnred(const float* __restrict__ gamma, const float* __restrict__ beta) {
  __shared__ float s[4][128];
  __shared__ float tot[128];
  const int tid = threadIdx.x;           // 512
  const int slot = tid & 127, part = tid >> 7;
  float sum = 0.f;
  for (int b = part; b < 3072; b += 4) sum += g_bnpart[(size_t)b*128 + slot];
  s[part][slot] = sum;
  __syncthreads();
  if (tid < 128) tot[tid] = s[0][tid] + s[1][tid] + s[2][tid] + s[3][tid];
  __syncthreads();
  if (tid < 64) {
    const float inv = 1.0f / 204800.0f;
    float mean = tot[tid] * inv;
    float var  = tot[64 + tid] * inv - mean*mean;
    float a = gamma[tid] * rsqrtf(var + 1e-5f);
    g_bn[tid]      = a;
    g_bn[64 + tid] = beta[tid] - mean * a;
  }
}

// ---------------- kernel D: epilogue ----------------
__global__ void k_out(const float* __restrict__ x, float* __restrict__ out) {
  const float4* z4 = (const float4*)g_z;
  const float4* x4 = (const float4*)x;
  float4* o4 = (float4*)out;
  const int total = (N_*C_*T_*V_) / 4;
  for (int i = blockIdx.x*blockDim.x + threadIdx.x; i < total; i += gridDim.x*blockDim.x) {
    int c = (i / 800) & 63;
    float a = g_bn[c], b = g_bn[64 + c];
    float4 z = z4[i], xx = x4[i], r;
    float v;
    v = z.x*a + b + xx.x; r.x = fmaxf(v, 0.1f*v);
    v = z.y*a + b + xx.y; r.y = fmaxf(v, 0.1f*v);
    v = z.z*a + b + xx.z; r.z = fmaxf(v, 0.1f*v);
    v = z.w*a + b + xx.w; r.w = fmaxf(v, 0.1f*v);
    o4[i] = r;
  }
}

// ---------------- launch ----------------
extern "C" void kernel_launch(void* const* d_in, const int* in_sizes, int n_in,
                              void* d_out, int out_size) {
  const float* x      = (const float*)d_in[0];
  const float* Wqkv   = (const float*)d_in[1];
  const float* bqkv   = (const float*)d_in[2];
  const float* alphas = (const float*)d_in[3];
  const float* att0s  = (const float*)d_in[4];
  const float* Wout   = (const float*)d_in[5];
  const float* bout   = (const float*)d_in[6];
  const float* gamma  = (const float*)d_in[7];
  const float* beta   = (const float*)d_in[8];
  float* out = (float*)d_out;

  cudaFuncSetAttribute(k_qkatt, cudaFuncAttributeMaxDynamicSharedMemorySize, 75776);
  cudaFuncSetAttribute(k_main,  cudaFuncAttributeMaxDynamicSharedMemorySize, 229584);

  k_init<<<64, 256>>>(Wqkv, Wout);
  k_qkatt<<<dim3(8, 64), 384, 75776>>>(x, bqkv);
  k_att2<<<(N_*1875 + 255)/256, 256>>>(alphas, att0s);
  k_main<<<dim3(16, 64), 512, 229584>>>(x, bout);
  k_bnred<<<1, 512>>>(gamma, beta);
  k_out<<<4096, 256>>>(x, out);
}

// round 8
// speedup vs baseline: 1.4373x; 1.3003x over previous
#include <cuda_runtime.h>
#include <cuda_bf16.h>
#include <cstdint>

#define N_  64
#define C_  64
#define T_  128
#define V_  25
#define H_  3
#define O_  192

typedef unsigned long long ull;

// ---------------- scratch ----------------
__device__ __align__(16) float g_pe[C_*V_];
__device__ __align__(16) float g_WqkvT[C_*O_];
__device__ __align__(16) float g_attpart[64*8*300*26];
__device__ __align__(16) float g_att[N_*H_*V_*V_];
__device__ __align__(16) float g_z[N_*C_*T_*V_];
__device__ __align__(16) float g_bnpart[64*128];
__device__ __align__(16) float g_bn[128];
// per dv: [term(hi/lo)][co=64][colp=200] bf16 = 51200 B = 3200 uint4
__device__ __align__(16) uint4 g_Wimg[5][3200];

// ---------------- f32x2 helpers ----------------
static __device__ __forceinline__ ull pack2(float a, float b){
  ull r; asm("mov.b64 %0, {%1, %2};" : "=l"(r) : "f"(a), "f"(b)); return r;
}
static __device__ __forceinline__ void fma2(ull& d, ull a, ull b){
  asm("fma.rn.f32x2 %0, %1, %2, %0;" : "+l"(d) : "l"(a), "l"(b));
}
static __device__ __forceinline__ float lo2(ull v){ return __uint_as_float((unsigned)v); }
static __device__ __forceinline__ float hi2(ull v){ return __uint_as_float((unsigned)(v>>32)); }

// ---------------- portable tensor-core helpers (sm_80+ baseline PTX) ----------------
static __device__ __forceinline__ uint32_t smem_to_u32(const void* p) {
  uint32_t a;
  asm("{ .reg .u64 t; cvta.to.shared.u64 t, %1; cvt.u32.u64 %0, t; }" : "=r"(a) : "l"(p));
  return a;
}
static __device__ __forceinline__ void ldm_x4(uint32_t* r, uint32_t addr){
  asm volatile("ldmatrix.sync.aligned.m8n8.x4.shared.b16 {%0,%1,%2,%3}, [%4];"
    : "=r"(r[0]), "=r"(r[1]), "=r"(r[2]), "=r"(r[3]) : "r"(addr));
}
static __device__ __forceinline__ void mma_bf16(float* d, const uint32_t* a, const uint32_t* b){
  asm volatile("mma.sync.aligned.m16n8k16.row.col.f32.bf16.bf16.f32 "
    "{%0,%1,%2,%3}, {%4,%5,%6,%7}, {%8,%9}, {%0,%1,%2,%3};"
    : "+f"(d[0]), "+f"(d[1]), "+f"(d[2]), "+f"(d[3])
    : "r"(a[0]), "r"(a[1]), "r"(a[2]), "r"(a[3]), "r"(b[0]), "r"(b[1]));
}

// ---------------- init ----------------
__global__ void k_init(const float* __restrict__ Wqkv, const float* __restrict__ Wout) {
  const int stride = gridDim.x * blockDim.x;
  const int i0 = blockIdx.x * blockDim.x + threadIdx.x;
  for (int i = i0; i < C_*V_; i += stride) {
    int c = i / V_, v = i - (i / V_) * V_;
    int ii = c >> 1;
    float dv = __expf(-(2.0f * ii) * (logf(10000.0f) / 64.0f));
    float ang = (float)v * dv;
    g_pe[i] = (c & 1) ? cosf(ang) : sinf(ang);
  }
  for (int i = i0; i < C_*O_; i += stride) {
    int c = i / O_, o = i - (i / O_) * O_;
    g_WqkvT[i] = Wqkv[o * C_ + c];
  }
  // g_Wimg: [dv][term][co][cp] bf16, cp 192..199 zero
  __nv_bfloat16* wb = (__nv_bfloat16*)g_Wimg;
  for (int i = i0; i < 5*2*64*200; i += stride) {
    int dv = i / 25600; int r = i - dv*25600;
    int term = r / 12800; r -= term*12800;
    int co = r / 200; int cp = r - co*200;
    float w = (cp < 192) ? Wout[co*960 + cp*5 + dv] : 0.f;
    __nv_bfloat16 hb = __float2bfloat16(w);
    wb[i] = (term == 0) ? hb : __float2bfloat16(w - __bfloat162float(hb));
  }
}

// ---------------- kernel A: QK GEMM + Gram (known good) ----------------
__global__ __launch_bounds__(384, 2) void k_qkatt(const float* __restrict__ x,
                                                  const float* __restrict__ bqkv) {
  extern __shared__ float sm[];
  float* sW  = sm;
  float* sxs = sW + 12288;
  float* sqk = sxs + 1664;
  const int tid = threadIdx.x;
  const int n = blockIdx.y, tc = blockIdx.x;

  for (int i = tid; i < 12288; i += 384) sW[i] = g_WqkvT[i];
  if (tid < 64) sxs[tid*26 + 25] = 0.f;
  if (tid < 192) sqk[tid*26 + 25] = 0.f;

  const int o = tid % 192;
  const int part = tid / 192;
  const int j0 = part ? 7 : 0;
  const float bo = bqkv[o];

  const int grow = tid >> 2, gcq = tid & 3;
  const bool gact = (tid < 300);
  const int gh = grow / 25, gu = grow - (grow/25)*25;
  ull gacc[13];
  #pragma unroll
  for (int j = 0; j < 13; ++j) gacc[j] = 0ULL;

  const int tbeg = tc * 16;
  for (int t = tbeg; t < tbeg + 16; ++t) {
    __syncthreads();
    for (int i = tid; i < 1600; i += 384) {
      int c = i / 25, v = i - c*25;
      sxs[c*26 + v] = x[(((size_t)n*C_ + c)*T_ + t)*V_ + v] + g_pe[i];
    }
    __syncthreads();
    {
      ull a2[7];
      ull binit = pack2(bo, bo);
      #pragma unroll
      for (int jj = 0; jj < 7; ++jj) a2[jj] = binit;
      const float* wp = sW + o;
      #pragma unroll 4
      for (int c = 0; c < 64; ++c) {
        float w = wp[c*192];
        ull w2 = pack2(w, w);
        const ull* xr = (const ull*)(sxs + c*26) + j0;
        #pragma unroll
        for (int jj = 0; jj < 7; ++jj) fma2(a2[jj], w2, xr[jj]);
      }
      float* q = sqk + o*26;
      if (part == 0) {
        #pragma unroll
        for (int jj = 0; jj < 7; ++jj) { q[2*jj] = lo2(a2[jj]); q[2*jj+1] = hi2(a2[jj]); }
      } else {
        #pragma unroll
        for (int jj = 0; jj < 5; ++jj) {
          q[14+2*jj] = lo2(a2[jj]); q[15+2*jj] = hi2(a2[jj]);
        }
        q[24] = lo2(a2[5]);
      }
    }
    __syncthreads();
    if (gact) {
      #pragma unroll
      for (int c8 = 0; c8 < 8; ++c8) {
        int c = gcq*8 + c8;
        float qv = sqk[(gh*32 + c)*26 + gu];
        ull q2 = pack2(qv, qv);
        const ull* kp = (const ull*)(sqk + (96 + gh*32 + c)*26);
        #pragma unroll
        for (int j = 0; j < 13; ++j) fma2(gacc[j], q2, kp[j]);
      }
    }
  }
  if (gact) {
    ull* op = (ull*)(g_attpart + ((size_t)(n*8 + tc)*300 + tid)*26);
    #pragma unroll
    for (int j = 0; j < 13; ++j) op[j] = gacc[j];
  }
}

// ---------------- kernel A2 ----------------
__global__ void k_att2(const float* __restrict__ alphas, const float* __restrict__ att0s) {
  int i = blockIdx.x * blockDim.x + threadIdx.x;
  if (i >= N_*1875) return;
  int n = i / 1875, r = i - n*1875;
  int h = r / 625, rr = r - h*625;
  int u = rr / 25, v = rr - (rr/25)*25;
  int row = h*25 + u;
  float s = 0.f;
  #pragma unroll
  for (int tc = 0; tc < 8; ++tc)
    #pragma unroll
    for (int cq = 0; cq < 4; ++cq)
      s += g_attpart[((size_t)(n*8 + tc)*300 + row*4 + cq)*26 + v];
  g_att[i] = tanhf(s * (1.0f/4096.0f)) * alphas[h] + att0s[r];
}

// ---------------- kernel B: att-apply (FFMA2) + conv (mma.sync bf16 3-split) ----------------
// grid (32 tc, 64 n), 512 threads. smem bytes:
//  A_hi [128 rows x 400B] @0 | A_lo @51200 | B buf0 @102400 | B buf1 @153600
//  satt @204800 (8400 B); sx overlays @102400 during phase 1. total 213248.
__global__ __launch_bounds__(512, 1) void k_main(const float* __restrict__ x,
                                                 const float* __restrict__ bout) {
  extern __shared__ char smc[];
  const uint32_t sbase = smem_to_u32(smc);
  float* satt = (float*)(smc + 204800);
  float* sx   = (float*)(smc + 102400);

  const int tid = threadIdx.x;
  const int wid = tid >> 5, lane = tid & 31;
  const int n = blockIdx.y;
  const int t0 = blockIdx.x * 4;

  // zero A_hi + A_lo (102400 B = 6400 uint4)
  for (int i = tid; i < 6400; i += 512) ((uint4*)smc)[i] = make_uint4(0,0,0,0);

  for (int i = tid; i < 1875; i += 512) {
    int h = i / 625, r = i - h*625;
    int u = r / 25, v = r - (r/25)*25;
    satt[(h*25 + u)*28 + v] = g_att[(size_t)n*1875 + i];
  }
  for (int i = tid; i < 225; i += 512) { int row = i/3, c = 25 + (i - (i/3)*3); satt[row*28 + c] = 0.f; }

  {
    const float* xg = x + (((size_t)n*C_)*T_ + t0)*V_;
    for (int i = tid; i < 6400; i += 512) {
      int ci = i / 100, r = i - ci*100;
      sx[ci*101 + r] = xg[(size_t)ci*3200 + r];
    }
  }
  __syncthreads();

  // Phase 1: y[ch][t4][v] -> A[t4*32 + v + 2][ch] as bf16 hi/lo
  #pragma unroll
  for (int rep = 0; rep < 2; ++rep) {
    int task = tid + 512*rep;
    if (task < 768) {
      int h = task >> 8, t4 = (task >> 6) & 3, ci = task & 63;
      ull a2[13];
      #pragma unroll
      for (int j = 0; j < 13; ++j) a2[j] = 0ULL;
      const float* sxp = sx + ci*101 + t4*25;
      const float* ap0 = satt + h*25*28;
      #pragma unroll
      for (int u = 0; u < 25; ++u) {
        float xv = sxp[u];
        ull xp = pack2(xv, xv);
        const ull* ar = (const ull*)(ap0 + u*28);
        #pragma unroll
        for (int j = 0; j < 13; ++j) fma2(a2[j], xp, ar[j]);
      }
      const int ch = h*64 + ci;
      char* arow = smc + (t4*32 + 2)*400 + ch*2;
      #pragma unroll
      for (int v = 0; v < 25; ++v) {
        float yv = (v & 1) ? hi2(a2[v >> 1]) : lo2(a2[v >> 1]);
        __nv_bfloat16 hb = __float2bfloat16(yv);
        *(__nv_bfloat16*)(arow + v*400)         = hb;
        *(__nv_bfloat16*)(arow + v*400 + 51200) = __float2bfloat16(yv - __bfloat162float(hb));
      }
    }
  }
  __syncthreads();

  // stage B(dv=0)->buf0, B(dv=1)->buf1 (sx no longer needed)
  for (int i = tid; i < 6400; i += 512) {
    int b = i >= 3200;
    ((uint4*)(smc + 102400))[i] = g_Wimg[b][i - b*3200];
  }
  __syncthreads();

  // Phase 2: D[m'][co] = sum_dv A[m'+dv][:] . B_dv[co][:]  (3-term bf16 split)
  const int mband = wid >> 1, nhalf = wid & 1;
  const int r8 = lane & 7;
  const uint32_t aoff  = (uint32_t)((mband*16 + r8 + ((lane>>3)&1)*8)*400 + (lane>>4)*16);
  const uint32_t boff0 = (uint32_t)((nhalf*32 + r8 + ((lane>>4)&1)*8)*400 + ((lane>>3)&1)*16);

  float d[4][4];
  #pragma unroll
  for (int j = 0; j < 4; ++j)
    #pragma unroll
    for (int k = 0; k < 4; ++k) d[j][k] = 0.f;

  for (int dv = 0; dv < 5; ++dv) {
    const int b = dv & 1;
    const uint32_t bufb = sbase + 102400u + (uint32_t)b*51200u;
    #pragma unroll
    for (int term = 0; term < 3; ++term) {
      // term 0: Ah*Bh, 1: Al*Bh, 2: Ah*Bl
      const uint32_t abase = sbase + (term == 1 ? 51200u : 0u) + aoff + (uint32_t)dv*400u;
      const uint32_t bbase = bufb + (term == 2 ? 25600u : 0u) + boff0;
      #pragma unroll
      for (int kc = 0; kc < 12; ++kc) {
        uint32_t a[4], b0[4], b1[4];
        ldm_x4(a,  abase + kc*32);
        ldm_x4(b0, bbase + kc*32);
        ldm_x4(b1, bbase + 6400 + kc*32);
        mma_bf16(d[0], a, b0);
        mma_bf16(d[1], a, b0 + 2);
        mma_bf16(d[2], a, b1);
        mma_bf16(d[3], a, b1 + 2);
      }
    }
    if (dv < 3) {
      __syncthreads();
      for (int i = tid; i < 3200; i += 512)
        ((uint4*)(smc + 102400 + b*51200))[i] = g_Wimg[dv + 2][i];
      __syncthreads();
    }
  }

  // Epilogue: predicated direct stores with bias
  {
    const int g = lane >> 2;
    const int m0 = mband*16 + g;
    const int m1 = m0 + 8;
    const int t40 = m0 >> 5, v0 = m0 & 31;
    const int t41 = m1 >> 5, v1 = m1 & 31;
    const size_t zb = (size_t)n*204800;
    #pragma unroll
    for (int j = 0; j < 4; ++j) {
      int co = nhalf*32 + j*8 + (lane & 3)*2;
      float b0v = bout[co], b1v = bout[co + 1];
      if (v0 < 25) {
        size_t base = zb + (size_t)co*3200 + (t0 + t40)*25 + v0;
        g_z[base]        = d[j][0] + b0v;
        g_z[base + 3200] = d[j][1] + b1v;
      }
      if (v1 < 25) {
        size_t base = zb + (size_t)co*3200 + (t0 + t41)*25 + v1;
        g_z[base]        = d[j][2] + b0v;
        g_z[base + 3200] = d[j][3] + b1v;
      }
    }
  }
}

// ---------------- kernel C1: z stats (deterministic) ----------------
__global__ void k_zstat() {
  const int n = blockIdx.x;
  const int wid = threadIdx.x >> 5, lane = threadIdx.x & 31;   // 256 thr
  #pragma unroll
  for (int j = 0; j < 8; ++j) {
    int co = wid*8 + j;
    const float* zp = g_z + ((size_t)(n*C_ + co))*3200;
    float s = 0.f, q = 0.f;
    for (int i = lane; i < 3200; i += 32) { float v = zp[i]; s += v; q += v*v; }
    #pragma unroll
    for (int dd = 16; dd > 0; dd >>= 1) {
      s += __shfl_down_sync(0xffffffffu, s, dd);
      q += __shfl_down_sync(0xffffffffu, q, dd);
    }
    if (lane == 0) { g_bnpart[n*128 + co] = s; g_bnpart[n*128 + 64 + co] = q; }
  }
}

// ---------------- kernel C2: BN reduce ----------------
__global__ void k_bnred(const float* __restrict__ gamma, const float* __restrict__ beta) {
  __shared__ float tot[128];
  const int tid = threadIdx.x;   // 128
  float s = 0.f;
  for (int b = 0; b < 64; ++b) s += g_bnpart[b*128 + tid];
  tot[tid] = s;
  __syncthreads();
  if (tid < 64) {
    const float inv = 1.0f / 204800.0f;
    float mean = tot[tid] * inv;
    float var  = tot[64 + tid] * inv - mean*mean;
    float a = gamma[tid] * rsqrtf(var + 1e-5f);
    g_bn[tid]      = a;
    g_bn[64 + tid] = beta[tid] - mean * a;
  }
}

// ---------------- kernel D: epilogue ----------------
__global__ void k_out(const float* __restrict__ x, float* __restrict__ out) {
  const float4* z4 = (const float4*)g_z;
  const float4* x4 = (const float4*)x;
  float4* o4 = (float4*)out;
  const int total = (N_*C_*T_*V_) / 4;
  for (int i = blockIdx.x*blockDim.x + threadIdx.x; i < total; i += gridDim.x*blockDim.x) {
    int c = (i / 800) & 63;
    float a = g_bn[c], b = g_bn[64 + c];
    float4 z = z4[i], xx = x4[i], r;
    float v;
    v = z.x*a + b + xx.x; r.x = fmaxf(v, 0.1f*v);
    v = z.y*a + b + xx.y; r.y = fmaxf(v, 0.1f*v);
    v = z.z*a + b + xx.z; r.z = fmaxf(v, 0.1f*v);
    v = z.w*a + b + xx.w; r.w = fmaxf(v, 0.1f*v);
    o4[i] = r;
  }
}

// ---------------- launch ----------------
extern "C" void kernel_launch(void* const* d_in, const int* in_sizes, int n_in,
                              void* d_out, int out_size) {
  const float* x      = (const float*)d_in[0];
  const float* Wqkv   = (const float*)d_in[1];
  const float* bqkv   = (const float*)d_in[2];
  const float* alphas = (const float*)d_in[3];
  const float* att0s  = (const float*)d_in[4];
  const float* Wout   = (const float*)d_in[5];
  const float* bout   = (const float*)d_in[6];
  const float* gamma  = (const float*)d_in[7];
  const float* beta   = (const float*)d_in[8];
  float* out = (float*)d_out;

  cudaFuncSetAttribute(k_qkatt, cudaFuncAttributeMaxDynamicSharedMemorySize, 75776);
  cudaFuncSetAttribute(k_main,  cudaFuncAttributeMaxDynamicSharedMemorySize, 213248);

  k_init<<<64, 256>>>(Wqkv, Wout);
  k_qkatt<<<dim3(8, 64), 384, 75776>>>(x, bqkv);
  k_att2<<<(N_*1875 + 255)/256, 256>>>(alphas, att0s);
  k_main<<<dim3(32, 64), 512, 213248>>>(x, bout);
  k_zstat<<<64, 256>>>();
  k_bnred<<<1, 128>>>(gamma, beta);
  k_out<<<4096, 256>>>(x, out);
}

// round 9
// speedup vs baseline: 1.6720x; 1.1633x over previous
#include <cuda_runtime.h>
#include <cuda_bf16.h>
#include <cstdint>

#define N_  64
#define C_  64
#define T_  128
#define V_  25
#define H_  3
#define O_  192

typedef unsigned long long ull;

// ---------------- scratch ----------------
__device__ __align__(16) float g_pe[C_*V_];
__device__ __align__(16) float g_WqkvT[C_*O_];
__device__ __align__(16) float g_attpart[64*8*300*26];
__device__ __align__(16) float g_att[N_*H_*V_*V_];
__device__ __align__(16) float g_z[N_*C_*T_*V_];
__device__ __align__(16) float g_bnpart[64*128];
__device__ __align__(16) float g_bn[128];
// per dv: [term(hi/lo)][co=64][colp=200] bf16 = 51200 B = 3200 uint4
__device__ __align__(16) uint4 g_Wimg[5][3200];

// ---------------- f32x2 helpers ----------------
static __device__ __forceinline__ ull pack2(float a, float b){
  ull r; asm("mov.b64 %0, {%1, %2};" : "=l"(r) : "f"(a), "f"(b)); return r;
}
static __device__ __forceinline__ void fma2(ull& d, ull a, ull b){
  asm("fma.rn.f32x2 %0, %1, %2, %0;" : "+l"(d) : "l"(a), "l"(b));
}
static __device__ __forceinline__ float lo2(ull v){ return __uint_as_float((unsigned)v); }
static __device__ __forceinline__ float hi2(ull v){ return __uint_as_float((unsigned)(v>>32)); }

// ---------------- portable tensor-core helpers (sm_80+ baseline PTX) ----------------
static __device__ __forceinline__ uint32_t smem_to_u32(const void* p) {
  uint32_t a;
  asm("{ .reg .u64 t; cvta.to.shared.u64 t, %1; cvt.u32.u64 %0, t; }" : "=r"(a) : "l"(p));
  return a;
}
static __device__ __forceinline__ void ldm_x4(uint32_t* r, uint32_t addr){
  asm volatile("ldmatrix.sync.aligned.m8n8.x4.shared.b16 {%0,%1,%2,%3}, [%4];"
    : "=r"(r[0]), "=r"(r[1]), "=r"(r[2]), "=r"(r[3]) : "r"(addr));
}
static __device__ __forceinline__ void mma_bf16(float* d, const uint32_t* a, const uint32_t* b){
  asm volatile("mma.sync.aligned.m16n8k16.row.col.f32.bf16.bf16.f32 "
    "{%0,%1,%2,%3}, {%4,%5,%6,%7}, {%8,%9}, {%0,%1,%2,%3};"
    : "+f"(d[0]), "+f"(d[1]), "+f"(d[2]), "+f"(d[3])
    : "r"(a[0]), "r"(a[1]), "r"(a[2]), "r"(a[3]), "r"(b[0]), "r"(b[1]));
}

// ---------------- init ----------------
__global__ void k_init(const float* __restrict__ Wqkv, const float* __restrict__ Wout) {
  const int stride = gridDim.x * blockDim.x;
  const int i0 = blockIdx.x * blockDim.x + threadIdx.x;
  for (int i = i0; i < C_*V_; i += stride) {
    int c = i / V_, v = i - (i / V_) * V_;
    int ii = c >> 1;
    float dv = __expf(-(2.0f * ii) * (logf(10000.0f) / 64.0f));
    float ang = (float)v * dv;
    g_pe[i] = (c & 1) ? cosf(ang) : sinf(ang);
  }
  for (int i = i0; i < C_*O_; i += stride) {
    int c = i / O_, o = i - (i / O_) * O_;
    g_WqkvT[i] = Wqkv[o * C_ + c];
  }
  // g_Wimg: [dv][term][co][cp] bf16, cp 192..199 zero
  __nv_bfloat16* wb = (__nv_bfloat16*)g_Wimg;
  for (int i = i0; i < 5*2*64*200; i += stride) {
    int dv = i / 25600; int r = i - dv*25600;
    int term = r / 12800; r -= term*12800;
    int co = r / 200; int cp = r - co*200;
    float w = (cp < 192) ? Wout[co*960 + cp*5 + dv] : 0.f;
    __nv_bfloat16 hb = __float2bfloat16(w);
    wb[i] = (term == 0) ? hb : __float2bfloat16(w - __bfloat162float(hb));
  }
}

// ---------------- kernel A: QK GEMM + Gram (known good) ----------------
__global__ __launch_bounds__(384, 2) void k_qkatt(const float* __restrict__ x,
                                                  const float* __restrict__ bqkv) {
  extern __shared__ float sm[];
  float* sW  = sm;
  float* sxs = sW + 12288;
  float* sqk = sxs + 1664;
  const int tid = threadIdx.x;
  const int n = blockIdx.y, tc = blockIdx.x;

  for (int i = tid; i < 12288; i += 384) sW[i] = g_WqkvT[i];
  if (tid < 64) sxs[tid*26 + 25] = 0.f;
  if (tid < 192) sqk[tid*26 + 25] = 0.f;

  const int o = tid % 192;
  const int part = tid / 192;
  const int j0 = part ? 7 : 0;
  const float bo = bqkv[o];

  const int grow = tid >> 2, gcq = tid & 3;
  const bool gact = (tid < 300);
  const int gh = grow / 25, gu = grow - (grow/25)*25;
  ull gacc[13];
  #pragma unroll
  for (int j = 0; j < 13; ++j) gacc[j] = 0ULL;

  const int tbeg = tc * 16;
  for (int t = tbeg; t < tbeg + 16; ++t) {
    __syncthreads();
    for (int i = tid; i < 1600; i += 384) {
      int c = i / 25, v = i - c*25;
      sxs[c*26 + v] = x[(((size_t)n*C_ + c)*T_ + t)*V_ + v] + g_pe[i];
    }
    __syncthreads();
    {
      ull a2[7];
      ull binit = pack2(bo, bo);
      #pragma unroll
      for (int jj = 0; jj < 7; ++jj) a2[jj] = binit;
      const float* wp = sW + o;
      #pragma unroll 4
      for (int c = 0; c < 64; ++c) {
        float w = wp[c*192];
        ull w2 = pack2(w, w);
        const ull* xr = (const ull*)(sxs + c*26) + j0;
        #pragma unroll
        for (int jj = 0; jj < 7; ++jj) fma2(a2[jj], w2, xr[jj]);
      }
      float* q = sqk + o*26;
      if (part == 0) {
        #pragma unroll
        for (int jj = 0; jj < 7; ++jj) { q[2*jj] = lo2(a2[jj]); q[2*jj+1] = hi2(a2[jj]); }
      } else {
        #pragma unroll
        for (int jj = 0; jj < 5; ++jj) {
          q[14+2*jj] = lo2(a2[jj]); q[15+2*jj] = hi2(a2[jj]);
        }
        q[24] = lo2(a2[5]);
      }
    }
    __syncthreads();
    if (gact) {
      #pragma unroll
      for (int c8 = 0; c8 < 8; ++c8) {
        int c = gcq*8 + c8;
        float qv = sqk[(gh*32 + c)*26 + gu];
        ull q2 = pack2(qv, qv);
        const ull* kp = (const ull*)(sqk + (96 + gh*32 + c)*26);
        #pragma unroll
        for (int j = 0; j < 13; ++j) fma2(gacc[j], q2, kp[j]);
      }
    }
  }
  if (gact) {
    ull* op = (ull*)(g_attpart + ((size_t)(n*8 + tc)*300 + tid)*26);
    #pragma unroll
    for (int j = 0; j < 13; ++j) op[j] = gacc[j];
  }
}

// ---------------- kernel A2 ----------------
__global__ void k_att2(const float* __restrict__ alphas, const float* __restrict__ att0s) {
  int i = blockIdx.x * blockDim.x + threadIdx.x;
  if (i >= N_*1875) return;
  int n = i / 1875, r = i - n*1875;
  int h = r / 625, rr = r - h*625;
  int u = rr / 25, v = rr - (rr/25)*25;
  int row = h*25 + u;
  float s = 0.f;
  #pragma unroll
  for (int tc = 0; tc < 8; ++tc)
    #pragma unroll
    for (int cq = 0; cq < 4; ++cq)
      s += g_attpart[((size_t)(n*8 + tc)*300 + row*4 + cq)*26 + v];
  g_att[i] = tanhf(s * (1.0f/4096.0f)) * alphas[h] + att0s[r];
}

// ---------------- kernel B: att-apply (FFMA2) + conv (mma.sync bf16 3-split) ----------------
// grid (32 tc, 64 n), 512 threads. smem bytes:
//  A_hi [128 rows x 400B] @0 | A_lo @51200 | B buf0 @102400 | B buf1 @153600
//  satt @204800 (8400 B); sx overlays @102400 during phase 1. total 213248.
__global__ __launch_bounds__(512, 1) void k_main(const float* __restrict__ x,
                                                 const float* __restrict__ bout) {
  extern __shared__ char smc[];
  const uint32_t sbase = smem_to_u32(smc);
  float* satt = (float*)(smc + 204800);
  float* sx   = (float*)(smc + 102400);

  const int tid = threadIdx.x;
  const int wid = tid >> 5, lane = tid & 31;
  const int n = blockIdx.y;
  const int t0 = blockIdx.x * 4;

  // zero A_hi + A_lo (102400 B = 6400 uint4)
  for (int i = tid; i < 6400; i += 512) ((uint4*)smc)[i] = make_uint4(0,0,0,0);

  for (int i = tid; i < 1875; i += 512) {
    int h = i / 625, r = i - h*625;
    int u = r / 25, v = r - (r/25)*25;
    satt[(h*25 + u)*28 + v] = g_att[(size_t)n*1875 + i];
  }
  for (int i = tid; i < 225; i += 512) { int row = i/3, c = 25 + (i - (i/3)*3); satt[row*28 + c] = 0.f; }

  {
    const float* xg = x + (((size_t)n*C_)*T_ + t0)*V_;
    for (int i = tid; i < 6400; i += 512) {
      int ci = i / 100, r = i - ci*100;
      sx[ci*101 + r] = xg[(size_t)ci*3200 + r];
    }
  }
  __syncthreads();

  // Phase 1: y[ch][t4][v] -> A[t4*32 + v + 2][ch] as bf16 hi/lo
  #pragma unroll
  for (int rep = 0; rep < 2; ++rep) {
    int task = tid + 512*rep;
    if (task < 768) {
      int h = task >> 8, t4 = (task >> 6) & 3, ci = task & 63;
      ull a2[13];
      #pragma unroll
      for (int j = 0; j < 13; ++j) a2[j] = 0ULL;
      const float* sxp = sx + ci*101 + t4*25;
      const float* ap0 = satt + h*25*28;
      #pragma unroll
      for (int u = 0; u < 25; ++u) {
        float xv = sxp[u];
        ull xp = pack2(xv, xv);
        const ull* ar = (const ull*)(ap0 + u*28);
        #pragma unroll
        for (int j = 0; j < 13; ++j) fma2(a2[j], xp, ar[j]);
      }
      const int ch = h*64 + ci;
      char* arow = smc + (t4*32 + 2)*400 + ch*2;
      #pragma unroll
      for (int v = 0; v < 25; ++v) {
        float yv = (v & 1) ? hi2(a2[v >> 1]) : lo2(a2[v >> 1]);
        __nv_bfloat16 hb = __float2bfloat16(yv);
        *(__nv_bfloat16*)(arow + v*400)         = hb;
        *(__nv_bfloat16*)(arow + v*400 + 51200) = __float2bfloat16(yv - __bfloat162float(hb));
      }
    }
  }
  __syncthreads();

  // stage B(dv=0)->buf0, B(dv=1)->buf1 (sx no longer needed)
  for (int i = tid; i < 6400; i += 512) {
    int b = i >= 3200;
    ((uint4*)(smc + 102400))[i] = g_Wimg[b][i - b*3200];
  }
  __syncthreads();

  // Phase 2: D[m'][co] = sum_dv A[m'+dv][:] . B_dv[co][:]  (3-term bf16 split)
  // Hoisted fragment loads: per (dv,kc) 6 ldmatrix + 12 mma.
  const int mband = wid >> 1, nhalf = wid & 1;
  const int r8 = lane & 7;
  const uint32_t aoff  = (uint32_t)((mband*16 + r8 + ((lane>>3)&1)*8)*400 + (lane>>4)*16);
  const uint32_t boff0 = (uint32_t)((nhalf*32 + r8 + ((lane>>4)&1)*8)*400 + ((lane>>3)&1)*16);

  float d[4][4];
  #pragma unroll
  for (int j = 0; j < 4; ++j)
    #pragma unroll
    for (int k = 0; k < 4; ++k) d[j][k] = 0.f;

  for (int dv = 0; dv < 5; ++dv) {
    const int b = dv & 1;
    const uint32_t abase_h = sbase + aoff + (uint32_t)dv*400u;
    const uint32_t abase_l = abase_h + 51200u;
    const uint32_t bbase_h = sbase + 102400u + (uint32_t)b*51200u + boff0;
    const uint32_t bbase_l = bbase_h + 25600u;
    #pragma unroll
    for (int kc = 0; kc < 12; ++kc) {
      uint32_t ah[4], al[4], bh0[4], bh1[4], bl0[4], bl1[4];
      ldm_x4(ah,  abase_h + kc*32);
      ldm_x4(al,  abase_l + kc*32);
      ldm_x4(bh0, bbase_h + kc*32);
      ldm_x4(bh1, bbase_h + 6400 + kc*32);
      ldm_x4(bl0, bbase_l + kc*32);
      ldm_x4(bl1, bbase_l + 6400 + kc*32);
      // term 0: Ah*Bh
      mma_bf16(d[0], ah, bh0);
      mma_bf16(d[1], ah, bh0 + 2);
      mma_bf16(d[2], ah, bh1);
      mma_bf16(d[3], ah, bh1 + 2);
      // term 1: Al*Bh
      mma_bf16(d[0], al, bh0);
      mma_bf16(d[1], al, bh0 + 2);
      mma_bf16(d[2], al, bh1);
      mma_bf16(d[3], al, bh1 + 2);
      // term 2: Ah*Bl
      mma_bf16(d[0], ah, bl0);
      mma_bf16(d[1], ah, bl0 + 2);
      mma_bf16(d[2], ah, bl1);
      mma_bf16(d[3], ah, bl1 + 2);
    }
    if (dv < 3) {
      __syncthreads();
      for (int i = tid; i < 3200; i += 512)
        ((uint4*)(smc + 102400 + b*51200))[i] = g_Wimg[dv + 2][i];
      __syncthreads();
    }
  }

  // Epilogue: predicated direct stores with bias
  {
    const int g = lane >> 2;
    const int m0 = mband*16 + g;
    const int m1 = m0 + 8;
    const int t40 = m0 >> 5, v0 = m0 & 31;
    const int t41 = m1 >> 5, v1 = m1 & 31;
    const size_t zb = (size_t)n*204800;
    #pragma unroll
    for (int j = 0; j < 4; ++j) {
      int co = nhalf*32 + j*8 + (lane & 3)*2;
      float b0v = bout[co], b1v = bout[co + 1];
      if (v0 < 25) {
        size_t base = zb + (size_t)co*3200 + (t0 + t40)*25 + v0;
        g_z[base]        = d[j][0] + b0v;
        g_z[base + 3200] = d[j][1] + b1v;
      }
      if (v1 < 25) {
        size_t base = zb + (size_t)co*3200 + (t0 + t41)*25 + v1;
        g_z[base]        = d[j][2] + b0v;
        g_z[base + 3200] = d[j][3] + b1v;
      }
    }
  }
}

// ---------------- kernel C1: z stats (deterministic) ----------------
__global__ void k_zstat() {
  const int n = blockIdx.x;
  const int wid = threadIdx.x >> 5, lane = threadIdx.x & 31;   // 256 thr
  #pragma unroll
  for (int j = 0; j < 8; ++j) {
    int co = wid*8 + j;
    const float* zp = g_z + ((size_t)(n*C_ + co))*3200;
    float s = 0.f, q = 0.f;
    for (int i = lane; i < 3200; i += 32) { float v = zp[i]; s += v; q += v*v; }
    #pragma unroll
    for (int dd = 16; dd > 0; dd >>= 1) {
      s += __shfl_down_sync(0xffffffffu, s, dd);
      q += __shfl_down_sync(0xffffffffu, q, dd);
    }
    if (lane == 0) { g_bnpart[n*128 + co] = s; g_bnpart[n*128 + 64 + co] = q; }
  }
}

// ---------------- kernel C2: BN reduce ----------------
__global__ void k_bnred(const float* __restrict__ gamma, const float* __restrict__ beta) {
  __shared__ float tot[128];
  const int tid = threadIdx.x;   // 128
  float s = 0.f;
  for (int b = 0; b < 64; ++b) s += g_bnpart[b*128 + tid];
  tot[tid] = s;
  __syncthreads();
  if (tid < 64) {
    const float inv = 1.0f / 204800.0f;
    float mean = tot[tid] * inv;
    float var  = tot[64 + tid] * inv - mean*mean;
    float a = gamma[tid] * rsqrtf(var + 1e-5f);
    g_bn[tid]      = a;
    g_bn[64 + tid] = beta[tid] - mean * a;
  }
}

// ---------------- kernel D: epilogue ----------------
__global__ void k_out(const float* __restrict__ x, float* __restrict__ out) {
  const float4* z4 = (const float4*)g_z;
  const float4* x4 = (const float4*)x;
  float4* o4 = (float4*)out;
  const int total = (N_*C_*T_*V_) / 4;
  for (int i = blockIdx.x*blockDim.x + threadIdx.x; i < total; i += gridDim.x*blockDim.x) {
    int c = (i / 800) & 63;
    float a = g_bn[c], b = g_bn[64 + c];
    float4 z = z4[i], xx = x4[i], r;
    float v;
    v = z.x*a + b + xx.x; r.x = fmaxf(v, 0.1f*v);
    v = z.y*a + b + xx.y; r.y = fmaxf(v, 0.1f*v);
    v = z.z*a + b + xx.z; r.z = fmaxf(v, 0.1f*v);
    v = z.w*a + b + xx.w; r.w = fmaxf(v, 0.1f*v);
    o4[i] = r;
  }
}

// ---------------- launch ----------------
extern "C" void kernel_launch(void* const* d_in, const int* in_sizes, int n_in,
                              void* d_out, int out_size) {
  const float* x      = (const float*)d_in[0];
  const float* Wqkv   = (const float*)d_in[1];
  const float* bqkv   = (const float*)d_in[2];
  const float* alphas = (const float*)d_in[3];
  const float* att0s  = (const float*)d_in[4];
  const float* Wout   = (const float*)d_in[5];
  const float* bout   = (const float*)d_in[6];
  const float* gamma  = (const float*)d_in[7];
  const float* beta   = (const float*)d_in[8];
  float* out = (float*)d_out;

  cudaFuncSetAttribute(k_qkatt, cudaFuncAttributeMaxDynamicSharedMemorySize, 75776);
  cudaFuncSetAttribute(k_main,  cudaFuncAttributeMaxDynamicSharedMemorySize, 213248);

  k_init<<<64, 256>>>(Wqkv, Wout);
  k_qkatt<<<dim3(8, 64), 384, 75776>>>(x, bqkv);
  k_att2<<<(N_*1875 + 255)/256, 256>>>(alphas, att0s);
  k_main<<<dim3(32, 64), 512, 213248>>>(x, bout);
  k_zstat<<<64, 256>>>();
  k_bnred<<<1, 128>>>(gamma, beta);
  k_out<<<4096, 256>>>(x, out);
}

// round 10
// speedup vs baseline: 1.8821x; 1.1256x over previous
#include <cuda_runtime.h>
#include <cuda_bf16.h>
#include <cuda_fp16.h>
#include <cstdint>

#define N_  64
#define C_  64
#define T_  128
#define V_  25
#define H_  3
#define O_  192

typedef unsigned long long ull;

// ---------------- scratch ----------------
__device__ __align__(16) float g_pe[C_*V_];
__device__ __align__(16) float g_WqkvT[C_*O_];
__device__ __align__(16) float g_attpart[64*8*300*26];
__device__ __align__(16) float g_att[N_*H_*V_*V_];
__device__ __align__(16) float g_z[N_*C_*T_*V_];
__device__ __align__(16) float g_bnpart[64*128];
__device__ __align__(16) float g_bn[128];
// per dv: [co=64][colp=200] fp16 = 25600 B = 1600 uint4
__device__ __align__(16) uint4 g_Wimg[5][1600];

// ---------------- f32x2 helpers ----------------
static __device__ __forceinline__ ull pack2(float a, float b){
  ull r; asm("mov.b64 %0, {%1, %2};" : "=l"(r) : "f"(a), "f"(b)); return r;
}
static __device__ __forceinline__ void fma2(ull& d, ull a, ull b){
  asm("fma.rn.f32x2 %0, %1, %2, %0;" : "+l"(d) : "l"(a), "l"(b));
}
static __device__ __forceinline__ float lo2(ull v){ return __uint_as_float((unsigned)v); }
static __device__ __forceinline__ float hi2(ull v){ return __uint_as_float((unsigned)(v>>32)); }

// ---------------- portable tensor-core helpers (sm_80+ baseline PTX) ----------------
static __device__ __forceinline__ uint32_t smem_to_u32(const void* p) {
  uint32_t a;
  asm("{ .reg .u64 t; cvta.to.shared.u64 t, %1; cvt.u32.u64 %0, t; }" : "=r"(a) : "l"(p));
  return a;
}
static __device__ __forceinline__ void ldm_x4(uint32_t* r, uint32_t addr){
  asm volatile("ldmatrix.sync.aligned.m8n8.x4.shared.b16 {%0,%1,%2,%3}, [%4];"
    : "=r"(r[0]), "=r"(r[1]), "=r"(r[2]), "=r"(r[3]) : "r"(addr));
}
static __device__ __forceinline__ void mma_f16(float* d, const uint32_t* a, const uint32_t* b){
  asm volatile("mma.sync.aligned.m16n8k16.row.col.f32.f16.f16.f32 "
    "{%0,%1,%2,%3}, {%4,%5,%6,%7}, {%8,%9}, {%0,%1,%2,%3};"
    : "+f"(d[0]), "+f"(d[1]), "+f"(d[2]), "+f"(d[3])
    : "r"(a[0]), "r"(a[1]), "r"(a[2]), "r"(a[3]), "r"(b[0]), "r"(b[1]));
}

// ---------------- init ----------------
__global__ void k_init(const float* __restrict__ Wqkv, const float* __restrict__ Wout) {
  const int stride = gridDim.x * blockDim.x;
  const int i0 = blockIdx.x * blockDim.x + threadIdx.x;
  for (int i = i0; i < C_*V_; i += stride) {
    int c = i / V_, v = i - (i / V_) * V_;
    int ii = c >> 1;
    float dv = __expf(-(2.0f * ii) * (logf(10000.0f) / 64.0f));
    float ang = (float)v * dv;
    g_pe[i] = (c & 1) ? cosf(ang) : sinf(ang);
  }
  for (int i = i0; i < C_*O_; i += stride) {
    int c = i / O_, o = i - (i / O_) * O_;
    g_WqkvT[i] = Wqkv[o * C_ + c];
  }
  // g_Wimg: [dv][co][cp] fp16, cp 192..199 zero
  __half* wb = (__half*)g_Wimg;
  for (int i = i0; i < 5*64*200; i += stride) {
    int dv = i / 12800; int r = i - dv*12800;
    int co = r / 200; int cp = r - co*200;
    float w = (cp < 192) ? Wout[co*960 + cp*5 + dv] : 0.f;
    wb[i] = __float2half(w);
  }
}

// ---------------- kernel A: QK GEMM + Gram (known good) ----------------
__global__ __launch_bounds__(384, 2) void k_qkatt(const float* __restrict__ x,
                                                  const float* __restrict__ bqkv) {
  extern __shared__ float sm[];
  float* sW  = sm;
  float* sxs = sW + 12288;
  float* sqk = sxs + 1664;
  const int tid = threadIdx.x;
  const int n = blockIdx.y, tc = blockIdx.x;

  for (int i = tid; i < 12288; i += 384) sW[i] = g_WqkvT[i];
  if (tid < 64) sxs[tid*26 + 25] = 0.f;
  if (tid < 192) sqk[tid*26 + 25] = 0.f;

  const int o = tid % 192;
  const int part = tid / 192;
  const int j0 = part ? 7 : 0;
  const float bo = bqkv[o];

  const int grow = tid >> 2, gcq = tid & 3;
  const bool gact = (tid < 300);
  const int gh = grow / 25, gu = grow - (grow/25)*25;
  ull gacc[13];
  #pragma unroll
  for (int j = 0; j < 13; ++j) gacc[j] = 0ULL;

  const int tbeg = tc * 16;
  for (int t = tbeg; t < tbeg + 16; ++t) {
    __syncthreads();
    for (int i = tid; i < 1600; i += 384) {
      int c = i / 25, v = i - c*25;
      sxs[c*26 + v] = x[(((size_t)n*C_ + c)*T_ + t)*V_ + v] + g_pe[i];
    }
    __syncthreads();
    {
      ull a2[7];
      ull binit = pack2(bo, bo);
      #pragma unroll
      for (int jj = 0; jj < 7; ++jj) a2[jj] = binit;
      const float* wp = sW + o;
      #pragma unroll 4
      for (int c = 0; c < 64; ++c) {
        float w = wp[c*192];
        ull w2 = pack2(w, w);
        const ull* xr = (const ull*)(sxs + c*26) + j0;
        #pragma unroll
        for (int jj = 0; jj < 7; ++jj) fma2(a2[jj], w2, xr[jj]);
      }
      float* q = sqk + o*26;
      if (part == 0) {
        #pragma unroll
        for (int jj = 0; jj < 7; ++jj) { q[2*jj] = lo2(a2[jj]); q[2*jj+1] = hi2(a2[jj]); }
      } else {
        #pragma unroll
        for (int jj = 0; jj < 5; ++jj) {
          q[14+2*jj] = lo2(a2[jj]); q[15+2*jj] = hi2(a2[jj]);
        }
        q[24] = lo2(a2[5]);
      }
    }
    __syncthreads();
    if (gact) {
      #pragma unroll
      for (int c8 = 0; c8 < 8; ++c8) {
        int c = gcq*8 + c8;
        float qv = sqk[(gh*32 + c)*26 + gu];
        ull q2 = pack2(qv, qv);
        const ull* kp = (const ull*)(sqk + (96 + gh*32 + c)*26);
        #pragma unroll
        for (int j = 0; j < 13; ++j) fma2(gacc[j], q2, kp[j]);
      }
    }
  }
  if (gact) {
    ull* op = (ull*)(g_attpart + ((size_t)(n*8 + tc)*300 + tid)*26);
    #pragma unroll
    for (int j = 0; j < 13; ++j) op[j] = gacc[j];
  }
}

// ---------------- kernel A2 ----------------
__global__ void k_att2(const float* __restrict__ alphas, const float* __restrict__ att0s) {
  int i = blockIdx.x * blockDim.x + threadIdx.x;
  if (i >= N_*1875) return;
  int n = i / 1875, r = i - n*1875;
  int h = r / 625, rr = r - h*625;
  int u = rr / 25, v = rr - (rr/25)*25;
  int row = h*25 + u;
  float s = 0.f;
  #pragma unroll
  for (int tc = 0; tc < 8; ++tc)
    #pragma unroll
    for (int cq = 0; cq < 4; ++cq)
      s += g_attpart[((size_t)(n*8 + tc)*300 + row*4 + cq)*26 + v];
  g_att[i] = tanhf(s * (1.0f/4096.0f)) * alphas[h] + att0s[r];
}

// ---------------- kernel B: att-apply (FFMA2) + conv (mma.sync fp16 2-term) ----------------
// grid (32 tc, 64 n), 512 threads. smem bytes:
//  A_hi [128 rows x 400B] @0 | A_lo @51200 | B buf0 @102400 | B buf1 @128000
//  satt @153600 (8400 B); sx overlays @102400 during phase 1. total 162016.
__global__ __launch_bounds__(512, 1) void k_main(const float* __restrict__ x,
                                                 const float* __restrict__ bout) {
  extern __shared__ char smc[];
  const uint32_t sbase = smem_to_u32(smc);
  float* satt = (float*)(smc + 153600);
  float* sx   = (float*)(smc + 102400);

  const int tid = threadIdx.x;
  const int wid = tid >> 5, lane = tid & 31;
  const int n = blockIdx.y;
  const int t0 = blockIdx.x * 4;

  // zero A_hi + A_lo (102400 B = 6400 uint4)
  for (int i = tid; i < 6400; i += 512) ((uint4*)smc)[i] = make_uint4(0,0,0,0);

  for (int i = tid; i < 1875; i += 512) {
    int h = i / 625, r = i - h*625;
    int u = r / 25, v = r - (r/25)*25;
    satt[(h*25 + u)*28 + v] = g_att[(size_t)n*1875 + i];
  }
  for (int i = tid; i < 225; i += 512) { int row = i/3, c = 25 + (i - (i/3)*3); satt[row*28 + c] = 0.f; }

  {
    const float* xg = x + (((size_t)n*C_)*T_ + t0)*V_;
    for (int i = tid; i < 6400; i += 512) {
      int ci = i / 100, r = i - ci*100;
      sx[ci*101 + r] = xg[(size_t)ci*3200 + r];
    }
  }
  __syncthreads();

  // Phase 1: y[ch][t4][v] -> A[t4*32 + v + 2][ch] as fp16 hi/lo
  #pragma unroll
  for (int rep = 0; rep < 2; ++rep) {
    int task = tid + 512*rep;
    if (task < 768) {
      int h = task >> 8, t4 = (task >> 6) & 3, ci = task & 63;
      ull a2[13];
      #pragma unroll
      for (int j = 0; j < 13; ++j) a2[j] = 0ULL;
      const float* sxp = sx + ci*101 + t4*25;
      const float* ap0 = satt + h*25*28;
      #pragma unroll
      for (int u = 0; u < 25; ++u) {
        float xv = sxp[u];
        ull xp = pack2(xv, xv);
        const ull* ar = (const ull*)(ap0 + u*28);
        #pragma unroll
        for (int j = 0; j < 13; ++j) fma2(a2[j], xp, ar[j]);
      }
      const int ch = h*64 + ci;
      char* arow = smc + (t4*32 + 2)*400 + ch*2;
      #pragma unroll
      for (int v = 0; v < 25; ++v) {
        float yv = (v & 1) ? hi2(a2[v >> 1]) : lo2(a2[v >> 1]);
        __half hb = __float2half(yv);
        *(__half*)(arow + v*400)         = hb;
        *(__half*)(arow + v*400 + 51200) = __float2half(yv - __half2float(hb));
      }
    }
  }
  __syncthreads();

  // stage B(dv=0)->buf0, B(dv=1)->buf1 (sx no longer needed)
  for (int i = tid; i < 3200; i += 512) {
    int b = i >= 1600;
    ((uint4*)(smc + 102400))[i] = g_Wimg[b][i - b*1600];
  }
  __syncthreads();

  // Phase 2: D[m'][co] = sum_dv A[m'+dv][:] . B_dv[co][:]  (2-term fp16 split)
  // per (dv,kc): 4 ldmatrix.x4 + 8 mma.
  const int mband = wid >> 1, nhalf = wid & 1;
  const int r8 = lane & 7;
  const uint32_t aoff  = (uint32_t)((mband*16 + r8 + ((lane>>3)&1)*8)*400 + (lane>>4)*16);
  const uint32_t boff0 = (uint32_t)((nhalf*32 + r8 + ((lane>>4)&1)*8)*400 + ((lane>>3)&1)*16);

  float d[4][4];
  #pragma unroll
  for (int j = 0; j < 4; ++j)
    #pragma unroll
    for (int k = 0; k < 4; ++k) d[j][k] = 0.f;

  for (int dv = 0; dv < 5; ++dv) {
    const int b = dv & 1;
    const uint32_t abase_h = sbase + aoff + (uint32_t)dv*400u;
    const uint32_t abase_l = abase_h + 51200u;
    const uint32_t bbase   = sbase + 102400u + (uint32_t)b*25600u + boff0;
    #pragma unroll
    for (int kc = 0; kc < 12; ++kc) {
      uint32_t ah[4], al[4], b0[4], b1[4];
      ldm_x4(ah, abase_h + kc*32);
      ldm_x4(al, abase_l + kc*32);
      ldm_x4(b0, bbase + kc*32);
      ldm_x4(b1, bbase + 6400 + kc*32);
      // term 0: Ah*B
      mma_f16(d[0], ah, b0);
      mma_f16(d[1], ah, b0 + 2);
      mma_f16(d[2], ah, b1);
      mma_f16(d[3], ah, b1 + 2);
      // term 1: Al*B
      mma_f16(d[0], al, b0);
      mma_f16(d[1], al, b0 + 2);
      mma_f16(d[2], al, b1);
      mma_f16(d[3], al, b1 + 2);
    }
    if (dv < 3) {
      __syncthreads();
      for (int i = tid; i < 1600; i += 512)
        ((uint4*)(smc + 102400 + b*25600))[i] = g_Wimg[dv + 2][i];
      __syncthreads();
    }
  }

  // Epilogue: predicated direct stores with bias
  {
    const int g = lane >> 2;
    const int m0 = mband*16 + g;
    const int m1 = m0 + 8;
    const int t40 = m0 >> 5, v0 = m0 & 31;
    const int t41 = m1 >> 5, v1 = m1 & 31;
    const size_t zb = (size_t)n*204800;
    #pragma unroll
    for (int j = 0; j < 4; ++j) {
      int co = nhalf*32 + j*8 + (lane & 3)*2;
      float b0v = bout[co], b1v = bout[co + 1];
      if (v0 < 25) {
        size_t base = zb + (size_t)co*3200 + (t0 + t40)*25 + v0;
        g_z[base]        = d[j][0] + b0v;
        g_z[base + 3200] = d[j][1] + b1v;
      }
      if (v1 < 25) {
        size_t base = zb + (size_t)co*3200 + (t0 + t41)*25 + v1;
        g_z[base]        = d[j][2] + b0v;
        g_z[base + 3200] = d[j][3] + b1v;
      }
    }
  }
}

// ---------------- kernel C1: z stats (deterministic) ----------------
__global__ void k_zstat() {
  const int n = blockIdx.x;
  const int wid = threadIdx.x >> 5, lane = threadIdx.x & 31;   // 256 thr
  #pragma unroll
  for (int j = 0; j < 8; ++j) {
    int co = wid*8 + j;
    const float* zp = g_z + ((size_t)(n*C_ + co))*3200;
    float s = 0.f, q = 0.f;
    for (int i = lane; i < 3200; i += 32) { float v = zp[i]; s += v; q += v*v; }
    #pragma unroll
    for (int dd = 16; dd > 0; dd >>= 1) {
      s += __shfl_down_sync(0xffffffffu, s, dd);
      q += __shfl_down_sync(0xffffffffu, q, dd);
    }
    if (lane == 0) { g_bnpart[n*128 + co] = s; g_bnpart[n*128 + 64 + co] = q; }
  }
}

// ---------------- kernel C2: BN reduce ----------------
__global__ void k_bnred(const float* __restrict__ gamma, const float* __restrict__ beta) {
  __shared__ float tot[128];
  const int tid = threadIdx.x;   // 128
  float s = 0.f;
  for (int b = 0; b < 64; ++b) s += g_bnpart[b*128 + tid];
  tot[tid] = s;
  __syncthreads();
  if (tid < 64) {
    const float inv = 1.0f / 204800.0f;
    float mean = tot[tid] * inv;
    float var  = tot[64 + tid] * inv - mean*mean;
    float a = gamma[tid] * rsqrtf(var + 1e-5f);
    g_bn[tid]      = a;
    g_bn[64 + tid] = beta[tid] - mean * a;
  }
}

// ---------------- kernel D: epilogue ----------------
__global__ void k_out(const float* __restrict__ x, float* __restrict__ out) {
  const float4* z4 = (const float4*)g_z;
  const float4* x4 = (const float4*)x;
  float4* o4 = (float4*)out;
  const int total = (N_*C_*T_*V_) / 4;
  for (int i = blockIdx.x*blockDim.x + threadIdx.x; i < total; i += gridDim.x*blockDim.x) {
    int c = (i / 800) & 63;
    float a = g_bn[c], b = g_bn[64 + c];
    float4 z = z4[i], xx = x4[i], r;
    float v;
    v = z.x*a + b + xx.x; r.x = fmaxf(v, 0.1f*v);
    v = z.y*a + b + xx.y; r.y = fmaxf(v, 0.1f*v);
    v = z.z*a + b + xx.z; r.z = fmaxf(v, 0.1f*v);
    v = z.w*a + b + xx.w; r.w = fmaxf(v, 0.1f*v);
    o4[i] = r;
  }
}

// ---------------- launch ----------------
extern "C" void kernel_launch(void* const* d_in, const int* in_sizes, int n_in,
                              void* d_out, int out_size) {
  const float* x      = (const float*)d_in[0];
  const float* Wqkv   = (const float*)d_in[1];
  const float* bqkv   = (const float*)d_in[2];
  const float* alphas = (const float*)d_in[3];
  const float* att0s  = (const float*)d_in[4];
  const float* Wout   = (const float*)d_in[5];
  const float* bout   = (const float*)d_in[6];
  const float* gamma  = (const float*)d_in[7];
  const float* beta   = (const float*)d_in[8];
  float* out = (float*)d_out;

  cudaFuncSetAttribute(k_qkatt, cudaFuncAttributeMaxDynamicSharedMemorySize, 75776);
  cudaFuncSetAttribute(k_main,  cudaFuncAttributeMaxDynamicSharedMemorySize, 162016);

  k_init<<<64, 256>>>(Wqkv, Wout);
  k_qkatt<<<dim3(8, 64), 384, 75776>>>(x, bqkv);
  k_att2<<<(N_*1875 + 255)/256, 256>>>(alphas, att0s);
  k_main<<<dim3(32, 64), 512, 162016>>>(x, bout);
  k_zstat<<<64, 256>>>();
  k_bnred<<<1, 128>>>(gamma, beta);
  k_out<<<4096, 256>>>(x, out);
}

// round 11
// speedup vs baseline: 2.1784x; 1.1575x over previous
#include <cuda_runtime.h>
#include <cuda_bf16.h>
#include <cuda_fp16.h>
#include <cstdint>

#define N_  64
#define C_  64
#define T_  128
#define V_  25
#define H_  3
#define O_  192

typedef unsigned long long ull;

// ---------------- scratch ----------------
__device__ __align__(16) float g_pe[C_*V_];
__device__ __align__(16) float g_attpart[64*8*300*26];
__device__ __align__(16) float g_att[N_*H_*V_*V_];
__device__ __align__(16) float g_z[N_*C_*T_*V_];
__device__ __align__(16) float g_bnpart[64*128];
__device__ __align__(16) float g_bn[128];
// conv W per dv: [co=64][colp=200] fp16 = 25600 B = 1600 uint4
__device__ __align__(16) uint4 g_Wimg[5][1600];
// QKV W image: [term hi/lo][o=192][c=72pad] fp16 = 55296 B = 3456 uint4
__device__ __align__(16) uint4 g_WqkvImg[3456];

// ---------------- f32x2 helpers ----------------
static __device__ __forceinline__ ull pack2(float a, float b){
  ull r; asm("mov.b64 %0, {%1, %2};" : "=l"(r) : "f"(a), "f"(b)); return r;
}
static __device__ __forceinline__ void fma2(ull& d, ull a, ull b){
  asm("fma.rn.f32x2 %0, %1, %2, %0;" : "+l"(d) : "l"(a), "l"(b));
}
static __device__ __forceinline__ float lo2(ull v){ return __uint_as_float((unsigned)v); }
static __device__ __forceinline__ float hi2(ull v){ return __uint_as_float((unsigned)(v>>32)); }

// ---------------- portable tensor-core helpers (sm_80+ baseline PTX) ----------------
static __device__ __forceinline__ uint32_t smem_to_u32(const void* p) {
  uint32_t a;
  asm("{ .reg .u64 t; cvta.to.shared.u64 t, %1; cvt.u32.u64 %0, t; }" : "=r"(a) : "l"(p));
  return a;
}
static __device__ __forceinline__ void ldm_x4(uint32_t* r, uint32_t addr){
  asm volatile("ldmatrix.sync.aligned.m8n8.x4.shared.b16 {%0,%1,%2,%3}, [%4];"
    : "=r"(r[0]), "=r"(r[1]), "=r"(r[2]), "=r"(r[3]) : "r"(addr));
}
static __device__ __forceinline__ void mma_f16(float* d, const uint32_t* a, const uint32_t* b){
  asm volatile("mma.sync.aligned.m16n8k16.row.col.f32.f16.f16.f32 "
    "{%0,%1,%2,%3}, {%4,%5,%6,%7}, {%8,%9}, {%0,%1,%2,%3};"
    : "+f"(d[0]), "+f"(d[1]), "+f"(d[2]), "+f"(d[3])
    : "r"(a[0]), "r"(a[1]), "r"(a[2]), "r"(a[3]), "r"(b[0]), "r"(b[1]));
}

// ---------------- init ----------------
__global__ void k_init(const float* __restrict__ Wqkv, const float* __restrict__ Wout) {
  const int stride = gridDim.x * blockDim.x;
  const int i0 = blockIdx.x * blockDim.x + threadIdx.x;
  for (int i = i0; i < C_*V_; i += stride) {
    int c = i / V_, v = i - (i / V_) * V_;
    int ii = c >> 1;
    float dv = __expf(-(2.0f * ii) * (logf(10000.0f) / 64.0f));
    float ang = (float)v * dv;
    g_pe[i] = (c & 1) ? cosf(ang) : sinf(ang);
  }
  // QKV W image: hi term then lo term, [o][c] with c padded to 72 (zeros)
  {
    __half* wb = (__half*)g_WqkvImg;
    for (int i = i0; i < 2*192*72; i += stride) {
      int term = i / 13824; int r = i - term*13824;
      int o = r / 72, c = r - (r/72)*72;
      float w = (c < 64) ? Wqkv[o*64 + c] : 0.f;
      __half hb = __float2half(w);
      wb[i] = (term == 0) ? hb : __float2half(w - __half2float(hb));
    }
  }
  // conv W image: [dv][co][cp] fp16, cp 192..199 zero
  {
    __half* wb = (__half*)g_Wimg;
    for (int i = i0; i < 5*64*200; i += stride) {
      int dv = i / 12800; int r = i - dv*12800;
      int co = r / 200; int cp = r - co*200;
      float w = (cp < 192) ? Wout[co*960 + cp*5 + dv] : 0.f;
      wb[i] = __float2half(w);
    }
  }
}

// ---------------- kernel A: QK GEMM (mma.sync fp16 3-term) + scalar Gram ----------------
// grid (8 tc, 64 n), 384 threads (12 warps, one 16-row M-tile each).
// smem bytes: A(W) hi @0 lo @27648 | B(xs) hi @55296 lo @71424 (112 rows x 144B)
//             qk fp32 @87552: [192][pitch 106] = 81408. total 168960.
#define QKP 106
__global__ __launch_bounds__(384, 1) void k_qkatt(const float* __restrict__ x,
                                                  const float* __restrict__ bqkv) {
  extern __shared__ char sqc[];
  const uint32_t sbase = smem_to_u32(sqc);
  float* qk = (float*)(sqc + 87552);
  const int tid = threadIdx.x;
  const int wid = tid >> 5, lane = tid & 31;
  const int n = blockIdx.y, tc = blockIdx.x;
  const int t0 = tc * 16;

  // stage W images (55296 B)
  for (int i = tid; i < 3456; i += 384) ((uint4*)sqc)[i] = g_WqkvImg[i];

  // stage xs chunk 0: rows tl*26+v, cols c (fp16 hi/lo)
  {
    const float* xg = x + (((size_t)n*C_)*T_ + t0)*V_;
    for (int i = tid; i < 6400; i += 384) {
      int c = i / 100, r = i - c*100;
      int tl = r / 25, v = r - tl*25;
      float xv = xg[(size_t)c*3200 + r] + g_pe[c*25 + v];
      int boff = (tl*26 + v)*144 + c*2;
      __half hb = __float2half(xv);
      *(__half*)(sqc + 55296 + boff) = hb;
      *(__half*)(sqc + 71424 + boff) = __float2half(xv - __half2float(hb));
    }
  }
  __syncthreads();

  // hoist A fragments (W hi/lo), 4 k-steps each
  const int m0 = wid * 16;
  const uint32_t aoff = (uint32_t)((m0 + (lane&7) + ((lane>>3)&1)*8)*144 + (lane>>4)*16);
  uint32_t ah[4][4], al[4][4];
  #pragma unroll
  for (int kc = 0; kc < 4; ++kc) {
    ldm_x4(ah[kc], sbase + aoff + kc*32);
    ldm_x4(al[kc], sbase + 27648u + aoff + kc*32);
  }
  const int g = lane >> 2, c0 = (lane&3)*2;
  const float bq0 = bqkv[m0 + g];
  const float bq1 = bqkv[m0 + g + 8];

  // Gram slots
  const int grow = tid >> 2, gcq = tid & 3;
  const bool gact = (tid < 300);
  const int gh = grow / 25, gu = grow - (grow/25)*25;
  ull gacc[13];
  #pragma unroll
  for (int j = 0; j < 13; ++j) gacc[j] = 0ULL;

  const uint32_t bboff = (uint32_t)(((lane&7) + ((lane>>4)&1)*8)*144 + ((lane>>3)&1)*16);

  for (int ck = 0; ck < 4; ++ck) {
    // GEMM: qk[192][104] = W . xs  (3-term fp16 split)
    float d[14][4];
    #pragma unroll
    for (int nt = 0; nt < 14; ++nt)
      #pragma unroll
      for (int j = 0; j < 4; ++j) d[nt][j] = 0.f;

    #pragma unroll
    for (int p = 0; p < 7; ++p) {
      const uint32_t bb = sbase + 55296u + (uint32_t)p*2304u + bboff;
      #pragma unroll
      for (int kc = 0; kc < 4; ++kc) {
        uint32_t bh[4], bl[4];
        ldm_x4(bh, bb + kc*32);
        ldm_x4(bl, bb + 16128u + kc*32);
        mma_f16(d[2*p],   ah[kc], bh);
        mma_f16(d[2*p+1], ah[kc], bh + 2);
        mma_f16(d[2*p],   ah[kc], bl);
        mma_f16(d[2*p+1], ah[kc], bl + 2);
        mma_f16(d[2*p],   al[kc], bh);
        mma_f16(d[2*p+1], al[kc], bh + 2);
      }
    }
    // epilogue: write qk + bias (13 n8 tiles; tile 13 is pad, discarded)
    #pragma unroll
    for (int nt = 0; nt < 13; ++nt) {
      int col = nt*8 + c0;
      float* r0 = qk + (m0 + g)*QKP + col;
      float* r1 = qk + (m0 + g + 8)*QKP + col;
      r0[0] = d[nt][0] + bq0; r0[1] = d[nt][1] + bq0;
      r1[0] = d[nt][2] + bq1; r1[1] = d[nt][3] + bq1;
    }
    __syncthreads();

    // Gram: S[h][u][v] += sum_c q[h*32+c][u] * k[96+h*32+c][v], 4 t-locals
    if (gact) {
      #pragma unroll
      for (int tl = 0; tl < 4; ++tl) {
        #pragma unroll
        for (int c8 = 0; c8 < 8; ++c8) {
          int c = gcq*8 + c8;
          float qv = qk[(gh*32 + c)*QKP + tl*26 + gu];
          ull q2 = pack2(qv, qv);
          const ull* kp = (const ull*)(qk + (96 + gh*32 + c)*QKP) + tl*13;
          #pragma unroll
          for (int j = 0; j < 13; ++j) fma2(gacc[j], q2, kp[j]);
        }
      }
    }
    // stage next xs chunk
    if (ck < 3) {
      const float* xg = x + (((size_t)n*C_)*T_ + t0 + (ck+1)*4)*V_;
      for (int i = tid; i < 6400; i += 384) {
        int c = i / 100, r = i - c*100;
        int tl = r / 25, v = r - tl*25;
        float xv = xg[(size_t)c*3200 + r] + g_pe[c*25 + v];
        int boff = (tl*26 + v)*144 + c*2;
        __half hb = __float2half(xv);
        *(__half*)(sqc + 55296 + boff) = hb;
        *(__half*)(sqc + 71424 + boff) = __float2half(xv - __half2float(hb));
      }
    }
    __syncthreads();
  }

  if (gact) {
    ull* op = (ull*)(g_attpart + ((size_t)(n*8 + tc)*300 + tid)*26);
    #pragma unroll
    for (int j = 0; j < 13; ++j) op[j] = gacc[j];
  }
}

// ---------------- kernel A2 ----------------
__global__ void k_att2(const float* __restrict__ alphas, const float* __restrict__ att0s) {
  int i = blockIdx.x * blockDim.x + threadIdx.x;
  if (i >= N_*1875) return;
  int n = i / 1875, r = i - n*1875;
  int h = r / 625, rr = r - h*625;
  int u = rr / 25, v = rr - (rr/25)*25;
  int row = h*25 + u;
  float s = 0.f;
  #pragma unroll
  for (int tc = 0; tc < 8; ++tc)
    #pragma unroll
    for (int cq = 0; cq < 4; ++cq)
      s += g_attpart[((size_t)(n*8 + tc)*300 + row*4 + cq)*26 + v];
  g_att[i] = tanhf(s * (1.0f/4096.0f)) * alphas[h] + att0s[r];
}

// ---------------- kernel B: att-apply (FFMA2) + conv (mma.sync fp16 2-term) ----------------
// grid (32 tc, 64 n), 512 threads. smem bytes:
//  A_hi [128 rows x 400B] @0 | A_lo @51200 | B buf0 @102400 | B buf1 @128000
//  satt @153600 (8400 B); sx overlays @102400 during phase 1. total 162016.
__global__ __launch_bounds__(512, 1) void k_main(const float* __restrict__ x,
                                                 const float* __restrict__ bout) {
  extern __shared__ char smc[];
  const uint32_t sbase = smem_to_u32(smc);
  float* satt = (float*)(smc + 153600);
  float* sx   = (float*)(smc + 102400);

  const int tid = threadIdx.x;
  const int wid = tid >> 5, lane = tid & 31;
  const int n = blockIdx.y;
  const int t0 = blockIdx.x * 4;

  // zero A_hi + A_lo (102400 B = 6400 uint4)
  for (int i = tid; i < 6400; i += 512) ((uint4*)smc)[i] = make_uint4(0,0,0,0);

  for (int i = tid; i < 1875; i += 512) {
    int h = i / 625, r = i - h*625;
    int u = r / 25, v = r - (r/25)*25;
    satt[(h*25 + u)*28 + v] = g_att[(size_t)n*1875 + i];
  }
  for (int i = tid; i < 225; i += 512) { int row = i/3, c = 25 + (i - (i/3)*3); satt[row*28 + c] = 0.f; }

  {
    const float* xg = x + (((size_t)n*C_)*T_ + t0)*V_;
    for (int i = tid; i < 6400; i += 512) {
      int ci = i / 100, r = i - ci*100;
      sx[ci*101 + r] = xg[(size_t)ci*3200 + r];
    }
  }
  __syncthreads();

  // Phase 1: y[ch][t4][v] -> A[t4*32 + v + 2][ch] as fp16 hi/lo
  #pragma unroll
  for (int rep = 0; rep < 2; ++rep) {
    int task = tid + 512*rep;
    if (task < 768) {
      int h = task >> 8, t4 = (task >> 6) & 3, ci = task & 63;
      ull a2[13];
      #pragma unroll
      for (int j = 0; j < 13; ++j) a2[j] = 0ULL;
      const float* sxp = sx + ci*101 + t4*25;
      const float* ap0 = satt + h*25*28;
      #pragma unroll
      for (int u = 0; u < 25; ++u) {
        float xv = sxp[u];
        ull xp = pack2(xv, xv);
        const ull* ar = (const ull*)(ap0 + u*28);
        #pragma unroll
        for (int j = 0; j < 13; ++j) fma2(a2[j], xp, ar[j]);
      }
      const int ch = h*64 + ci;
      char* arow = smc + (t4*32 + 2)*400 + ch*2;
      #pragma unroll
      for (int v = 0; v < 25; ++v) {
        float yv = (v & 1) ? hi2(a2[v >> 1]) : lo2(a2[v >> 1]);
        __half hb = __float2half(yv);
        *(__half*)(arow + v*400)         = hb;
        *(__half*)(arow + v*400 + 51200) = __float2half(yv - __half2float(hb));
      }
    }
  }
  __syncthreads();

  // stage B(dv=0)->buf0, B(dv=1)->buf1 (sx no longer needed)
  for (int i = tid; i < 3200; i += 512) {
    int b = i >= 1600;
    ((uint4*)(smc + 102400))[i] = g_Wimg[b][i - b*1600];
  }
  __syncthreads();

  // Phase 2: D[m'][co] = sum_dv A[m'+dv][:] . B_dv[co][:]  (2-term fp16 split)
  const int mband = wid >> 1, nhalf = wid & 1;
  const int r8 = lane & 7;
  const uint32_t aoff  = (uint32_t)((mband*16 + r8 + ((lane>>3)&1)*8)*400 + (lane>>4)*16);
  const uint32_t boff0 = (uint32_t)((nhalf*32 + r8 + ((lane>>4)&1)*8)*400 + ((lane>>3)&1)*16);

  float d[4][4];
  #pragma unroll
  for (int j = 0; j < 4; ++j)
    #pragma unroll
    for (int k = 0; k < 4; ++k) d[j][k] = 0.f;

  for (int dv = 0; dv < 5; ++dv) {
    const int b = dv & 1;
    const uint32_t abase_h = sbase + aoff + (uint32_t)dv*400u;
    const uint32_t abase_l = abase_h + 51200u;
    const uint32_t bbase   = sbase + 102400u + (uint32_t)b*25600u + boff0;
    #pragma unroll
    for (int kc = 0; kc < 12; ++kc) {
      uint32_t ah[4], al[4], b0[4], b1[4];
      ldm_x4(ah, abase_h + kc*32);
      ldm_x4(al, abase_l + kc*32);
      ldm_x4(b0, bbase + kc*32);
      ldm_x4(b1, bbase + 6400 + kc*32);
      mma_f16(d[0], ah, b0);
      mma_f16(d[1], ah, b0 + 2);
      mma_f16(d[2], ah, b1);
      mma_f16(d[3], ah, b1 + 2);
      mma_f16(d[0], al, b0);
      mma_f16(d[1], al, b0 + 2);
      mma_f16(d[2], al, b1);
      mma_f16(d[3], al, b1 + 2);
    }
    if (dv < 3) {
      __syncthreads();
      for (int i = tid; i < 1600; i += 512)
        ((uint4*)(smc + 102400 + b*25600))[i] = g_Wimg[dv + 2][i];
      __syncthreads();
    }
  }

  // Epilogue: predicated direct stores with bias
  {
    const int g = lane >> 2;
    const int m0 = mband*16 + g;
    const int m1 = m0 + 8;
    const int t40 = m0 >> 5, v0 = m0 & 31;
    const int t41 = m1 >> 5, v1 = m1 & 31;
    const size_t zb = (size_t)n*204800;
    #pragma unroll
    for (int j = 0; j < 4; ++j) {
      int co = nhalf*32 + j*8 + (lane & 3)*2;
      float b0v = bout[co], b1v = bout[co + 1];
      if (v0 < 25) {
        size_t base = zb + (size_t)co*3200 + (t0 + t40)*25 + v0;
        g_z[base]        = d[j][0] + b0v;
        g_z[base + 3200] = d[j][1] + b1v;
      }
      if (v1 < 25) {
        size_t base = zb + (size_t)co*3200 + (t0 + t41)*25 + v1;
        g_z[base]        = d[j][2] + b0v;
        g_z[base + 3200] = d[j][3] + b1v;
      }
    }
  }
}

// ---------------- kernel C1: z stats (deterministic) ----------------
__global__ void k_zstat() {
  const int n = blockIdx.x;
  const int wid = threadIdx.x >> 5, lane = threadIdx.x & 31;   // 256 thr
  #pragma unroll
  for (int j = 0; j < 8; ++j) {
    int co = wid*8 + j;
    const float* zp = g_z + ((size_t)(n*C_ + co))*3200;
    float s = 0.f, q = 0.f;
    for (int i = lane; i < 3200; i += 32) { float v = zp[i]; s += v; q += v*v; }
    #pragma unroll
    for (int dd = 16; dd > 0; dd >>= 1) {
      s += __shfl_down_sync(0xffffffffu, s, dd);
      q += __shfl_down_sync(0xffffffffu, q, dd);
    }
    if (lane == 0) { g_bnpart[n*128 + co] = s; g_bnpart[n*128 + 64 + co] = q; }
  }
}

// ---------------- kernel C2: BN reduce ----------------
__global__ void k_bnred(const float* __restrict__ gamma, const float* __restrict__ beta) {
  __shared__ float tot[128];
  const int tid = threadIdx.x;   // 128
  float s = 0.f;
  for (int b = 0; b < 64; ++b) s += g_bnpart[b*128 + tid];
  tot[tid] = s;
  __syncthreads();
  if (tid < 64) {
    const float inv = 1.0f / 204800.0f;
    float mean = tot[tid] * inv;
    float var  = tot[64 + tid] * inv - mean*mean;
    float a = gamma[tid] * rsqrtf(var + 1e-5f);
    g_bn[tid]      = a;
    g_bn[64 + tid] = beta[tid] - mean * a;
  }
}

// ---------------- kernel D: epilogue ----------------
__global__ void k_out(const float* __restrict__ x, float* __restrict__ out) {
  const float4* z4 = (const float4*)g_z;
  const float4* x4 = (const float4*)x;
  float4* o4 = (float4*)out;
  const int total = (N_*C_*T_*V_) / 4;
  for (int i = blockIdx.x*blockDim.x + threadIdx.x; i < total; i += gridDim.x*blockDim.x) {
    int c = (i / 800) & 63;
    float a = g_bn[c], b = g_bn[64 + c];
    float4 z = z4[i], xx = x4[i], r;
    float v;
    v = z.x*a + b + xx.x; r.x = fmaxf(v, 0.1f*v);
    v = z.y*a + b + xx.y; r.y = fmaxf(v, 0.1f*v);
    v = z.z*a + b + xx.z; r.z = fmaxf(v, 0.1f*v);
    v = z.w*a + b + xx.w; r.w = fmaxf(v, 0.1f*v);
    o4[i] = r;
  }
}

// ---------------- launch ----------------
extern "C" void kernel_launch(void* const* d_in, const int* in_sizes, int n_in,
                              void* d_out, int out_size) {
  const float* x      = (const float*)d_in[0];
  const float* Wqkv   = (const float*)d_in[1];
  const float* bqkv   = (const float*)d_in[2];
  const float* alphas = (const float*)d_in[3];
  const float* att0s  = (const float*)d_in[4];
  const float* Wout   = (const float*)d_in[5];
  const float* bout   = (const float*)d_in[6];
  const float* gamma  = (const float*)d_in[7];
  const float* beta   = (const float*)d_in[8];
  float* out = (float*)d_out;

  cudaFuncSetAttribute(k_qkatt, cudaFuncAttributeMaxDynamicSharedMemorySize, 168960);
  cudaFuncSetAttribute(k_main,  cudaFuncAttributeMaxDynamicSharedMemorySize, 162016);

  k_init<<<64, 256>>>(Wqkv, Wout);
  k_qkatt<<<dim3(8, 64), 384, 168960>>>(x, bqkv);
  k_att2<<<(N_*1875 + 255)/256, 256>>>(alphas, att0s);
  k_main<<<dim3(32, 64), 512, 162016>>>(x, bout);
  k_zstat<<<64, 256>>>();
  k_bnred<<<1, 128>>>(gamma, beta);
  k_out<<<4096, 256>>>(x, out);
}

// round 12
// speedup vs baseline: 2.6315x; 1.2080x over previous
#include <cuda_runtime.h>
#include <cuda_bf16.h>
#include <cuda_fp16.h>
#include <cstdint>

#define N_  64
#define C_  64
#define T_  128
#define V_  25
#define H_  3
#define O_  192

typedef unsigned long long ull;

// ---------------- scratch ----------------
__device__ __align__(16) float g_pe[C_*V_];
__device__ __align__(16) float g_attpart[64*8*300*26];
__device__ __align__(16) float g_att[N_*H_*V_*V_];
__device__ __align__(16) float g_z[N_*C_*T_*V_];
__device__ __align__(16) float g_bnpart[64*128];
__device__ __align__(16) float g_bn[128];
// conv W per dv: [co=64][colp=200] fp16 = 25600 B = 1600 uint4
__device__ __align__(16) uint4 g_Wimg[5][1600];
// QKV W image: [term hi/lo][o=192][c=72pad] fp16 = 55296 B = 3456 uint4
__device__ __align__(16) uint4 g_WqkvImg[3456];

// ---------------- f32x2 helpers ----------------
static __device__ __forceinline__ ull pack2(float a, float b){
  ull r; asm("mov.b64 %0, {%1, %2};" : "=l"(r) : "f"(a), "f"(b)); return r;
}
static __device__ __forceinline__ void fma2(ull& d, ull a, ull b){
  asm("fma.rn.f32x2 %0, %1, %2, %0;" : "+l"(d) : "l"(a), "l"(b));
}
static __device__ __forceinline__ float lo2(ull v){ return __uint_as_float((unsigned)v); }
static __device__ __forceinline__ float hi2(ull v){ return __uint_as_float((unsigned)(v>>32)); }

// ---------------- portable tensor-core helpers (sm_80+ baseline PTX) ----------------
static __device__ __forceinline__ uint32_t smem_to_u32(const void* p) {
  uint32_t a;
  asm("{ .reg .u64 t; cvta.to.shared.u64 t, %1; cvt.u32.u64 %0, t; }" : "=r"(a) : "l"(p));
  return a;
}
static __device__ __forceinline__ void ldm_x4(uint32_t* r, uint32_t addr){
  asm volatile("ldmatrix.sync.aligned.m8n8.x4.shared.b16 {%0,%1,%2,%3}, [%4];"
    : "=r"(r[0]), "=r"(r[1]), "=r"(r[2]), "=r"(r[3]) : "r"(addr));
}
static __device__ __forceinline__ void mma_f16(float* d, const uint32_t* a, const uint32_t* b){
  asm volatile("mma.sync.aligned.m16n8k16.row.col.f32.f16.f16.f32 "
    "{%0,%1,%2,%3}, {%4,%5,%6,%7}, {%8,%9}, {%0,%1,%2,%3};"
    : "+f"(d[0]), "+f"(d[1]), "+f"(d[2]), "+f"(d[3])
    : "r"(a[0]), "r"(a[1]), "r"(a[2]), "r"(a[3]), "r"(b[0]), "r"(b[1]));
}

// ---------------- init ----------------
__global__ void k_init(const float* __restrict__ Wqkv, const float* __restrict__ Wout) {
  const int stride = gridDim.x * blockDim.x;
  const int i0 = blockIdx.x * blockDim.x + threadIdx.x;
  for (int i = i0; i < C_*V_; i += stride) {
    int c = i / V_, v = i - (i / V_) * V_;
    int ii = c >> 1;
    float dv = __expf(-(2.0f * ii) * (logf(10000.0f) / 64.0f));
    float ang = (float)v * dv;
    g_pe[i] = (c & 1) ? cosf(ang) : sinf(ang);
  }
  {
    __half* wb = (__half*)g_WqkvImg;
    for (int i = i0; i < 2*192*72; i += stride) {
      int term = i / 13824; int r = i - term*13824;
      int o = r / 72, c = r - (r/72)*72;
      float w = (c < 64) ? Wqkv[o*64 + c] : 0.f;
      __half hb = __float2half(w);
      wb[i] = (term == 0) ? hb : __float2half(w - __half2float(hb));
    }
  }
  {
    __half* wb = (__half*)g_Wimg;
    for (int i = i0; i < 5*64*200; i += stride) {
      int dv = i / 12800; int r = i - dv*12800;
      int co = r / 200; int cp = r - co*200;
      float w = (cp < 192) ? Wout[co*960 + cp*5 + dv] : 0.f;
      wb[i] = __float2half(w);
    }
  }
}

// ---------------- kernel A: QK GEMM (mma.sync fp16 3-term) + scalar Gram ----------------
#define QKP 106
__global__ __launch_bounds__(384, 1) void k_qkatt(const float* __restrict__ x,
                                                  const float* __restrict__ bqkv) {
  extern __shared__ char sqc[];
  const uint32_t sbase = smem_to_u32(sqc);
  float* qk = (float*)(sqc + 87552);
  const int tid = threadIdx.x;
  const int wid = tid >> 5, lane = tid & 31;
  const int n = blockIdx.y, tc = blockIdx.x;
  const int t0 = tc * 16;

  for (int i = tid; i < 3456; i += 384) ((uint4*)sqc)[i] = g_WqkvImg[i];

  {
    const float* xg = x + (((size_t)n*C_)*T_ + t0)*V_;
    for (int i = tid; i < 6400; i += 384) {
      int c = i / 100, r = i - c*100;
      int tl = r / 25, v = r - tl*25;
      float xv = xg[(size_t)c*3200 + r] + g_pe[c*25 + v];
      int boff = (tl*26 + v)*144 + c*2;
      __half hb = __float2half(xv);
      *(__half*)(sqc + 55296 + boff) = hb;
      *(__half*)(sqc + 71424 + boff) = __float2half(xv - __half2float(hb));
    }
  }
  __syncthreads();

  const int m0 = wid * 16;
  const uint32_t aoff = (uint32_t)((m0 + (lane&7) + ((lane>>3)&1)*8)*144 + (lane>>4)*16);
  uint32_t ah[4][4], al[4][4];
  #pragma unroll
  for (int kc = 0; kc < 4; ++kc) {
    ldm_x4(ah[kc], sbase + aoff + kc*32);
    ldm_x4(al[kc], sbase + 27648u + aoff + kc*32);
  }
  const int g = lane >> 2, c0 = (lane&3)*2;
  const float bq0 = bqkv[m0 + g];
  const float bq1 = bqkv[m0 + g + 8];

  const int grow = tid >> 2, gcq = tid & 3;
  const bool gact = (tid < 300);
  const int gh = grow / 25, gu = grow - (grow/25)*25;
  ull gacc[13];
  #pragma unroll
  for (int j = 0; j < 13; ++j) gacc[j] = 0ULL;

  const uint32_t bboff = (uint32_t)(((lane&7) + ((lane>>4)&1)*8)*144 + ((lane>>3)&1)*16);

  for (int ck = 0; ck < 4; ++ck) {
    float d[14][4];
    #pragma unroll
    for (int nt = 0; nt < 14; ++nt)
      #pragma unroll
      for (int j = 0; j < 4; ++j) d[nt][j] = 0.f;

    #pragma unroll
    for (int p = 0; p < 7; ++p) {
      const uint32_t bb = sbase + 55296u + (uint32_t)p*2304u + bboff;
      #pragma unroll
      for (int kc = 0; kc < 4; ++kc) {
        uint32_t bh[4], bl[4];
        ldm_x4(bh, bb + kc*32);
        ldm_x4(bl, bb + 16128u + kc*32);
        mma_f16(d[2*p],   ah[kc], bh);
        mma_f16(d[2*p+1], ah[kc], bh + 2);
        mma_f16(d[2*p],   ah[kc], bl);
        mma_f16(d[2*p+1], ah[kc], bl + 2);
        mma_f16(d[2*p],   al[kc], bh);
        mma_f16(d[2*p+1], al[kc], bh + 2);
      }
    }
    #pragma unroll
    for (int nt = 0; nt < 13; ++nt) {
      int col = nt*8 + c0;
      float* r0 = qk + (m0 + g)*QKP + col;
      float* r1 = qk + (m0 + g + 8)*QKP + col;
      r0[0] = d[nt][0] + bq0; r0[1] = d[nt][1] + bq0;
      r1[0] = d[nt][2] + bq1; r1[1] = d[nt][3] + bq1;
    }
    __syncthreads();

    if (gact) {
      #pragma unroll
      for (int tl = 0; tl < 4; ++tl) {
        #pragma unroll
        for (int c8 = 0; c8 < 8; ++c8) {
          int c = gcq*8 + c8;
          float qv = qk[(gh*32 + c)*QKP + tl*26 + gu];
          ull q2 = pack2(qv, qv);
          const ull* kp = (const ull*)(qk + (96 + gh*32 + c)*QKP) + tl*13;
          #pragma unroll
          for (int j = 0; j < 13; ++j) fma2(gacc[j], q2, kp[j]);
        }
      }
    }
    if (ck < 3) {
      const float* xg = x + (((size_t)n*C_)*T_ + t0 + (ck+1)*4)*V_;
      for (int i = tid; i < 6400; i += 384) {
        int c = i / 100, r = i - c*100;
        int tl = r / 25, v = r - tl*25;
        float xv = xg[(size_t)c*3200 + r] + g_pe[c*25 + v];
        int boff = (tl*26 + v)*144 + c*2;
        __half hb = __float2half(xv);
        *(__half*)(sqc + 55296 + boff) = hb;
        *(__half*)(sqc + 71424 + boff) = __float2half(xv - __half2float(hb));
      }
    }
    __syncthreads();
  }

  if (gact) {
    ull* op = (ull*)(g_attpart + ((size_t)(n*8 + tc)*300 + tid)*26);
    #pragma unroll
    for (int j = 0; j < 13; ++j) op[j] = gacc[j];
  }
}

// ---------------- kernel A2 ----------------
__global__ void k_att2(const float* __restrict__ alphas, const float* __restrict__ att0s) {
  int i = blockIdx.x * blockDim.x + threadIdx.x;
  if (i >= N_*1875) return;
  int n = i / 1875, r = i - n*1875;
  int h = r / 625, rr = r - h*625;
  int u = rr / 25, v = rr - (rr/25)*25;
  int row = h*25 + u;
  float s = 0.f;
  #pragma unroll
  for (int tc = 0; tc < 8; ++tc)
    #pragma unroll
    for (int cq = 0; cq < 4; ++cq)
      s += g_attpart[((size_t)(n*8 + tc)*300 + row*4 + cq)*26 + v];
  g_att[i] = tanhf(s * (1.0f/4096.0f)) * alphas[h] + att0s[r];
}

// ---------------- kernel B: att-apply (FFMA2) + conv (mma.sync fp16, A single-term) ----------------
// grid (32 tc, 64 n), 512 threads, 2 CTAs/SM. smem bytes:
//  A [128 rows x 400B] @0 | B buf0 @51200 | B buf1 @76800 | satt @102400 (8400 B)
//  sx overlays @51200 during phase 1. total 110800.
__global__ __launch_bounds__(512, 2) void k_main(const float* __restrict__ x,
                                                 const float* __restrict__ bout) {
  extern __shared__ char smc[];
  const uint32_t sbase = smem_to_u32(smc);
  float* satt = (float*)(smc + 102400);
  float* sx   = (float*)(smc + 51200);

  const int tid = threadIdx.x;
  const int wid = tid >> 5, lane = tid & 31;
  const int n = blockIdx.y;
  const int t0 = blockIdx.x * 4;

  // zero A (51200 B = 3200 uint4)
  for (int i = tid; i < 3200; i += 512) ((uint4*)smc)[i] = make_uint4(0,0,0,0);

  for (int i = tid; i < 1875; i += 512) {
    int h = i / 625, r = i - h*625;
    int u = r / 25, v = r - (r/25)*25;
    satt[(h*25 + u)*28 + v] = g_att[(size_t)n*1875 + i];
  }
  for (int i = tid; i < 225; i += 512) { int row = i/3, c = 25 + (i - (i/3)*3); satt[row*28 + c] = 0.f; }

  {
    const float* xg = x + (((size_t)n*C_)*T_ + t0)*V_;
    for (int i = tid; i < 6400; i += 512) {
      int ci = i / 100, r = i - ci*100;
      sx[ci*101 + r] = xg[(size_t)ci*3200 + r];
    }
  }
  __syncthreads();

  // Phase 1: y[ch][t4][v] -> A[t4*32 + v + 2][ch] as fp16 (single term)
  #pragma unroll
  for (int rep = 0; rep < 2; ++rep) {
    int task = tid + 512*rep;
    if (task < 768) {
      int h = task >> 8, t4 = (task >> 6) & 3, ci = task & 63;
      ull a2[13];
      #pragma unroll
      for (int j = 0; j < 13; ++j) a2[j] = 0ULL;
      const float* sxp = sx + ci*101 + t4*25;
      const float* ap0 = satt + h*25*28;
      #pragma unroll
      for (int u = 0; u < 25; ++u) {
        float xv = sxp[u];
        ull xp = pack2(xv, xv);
        const ull* ar = (const ull*)(ap0 + u*28);
        #pragma unroll
        for (int j = 0; j < 13; ++j) fma2(a2[j], xp, ar[j]);
      }
      const int ch = h*64 + ci;
      char* arow = smc + (t4*32 + 2)*400 + ch*2;
      #pragma unroll
      for (int v = 0; v < 25; ++v) {
        float yv = (v & 1) ? hi2(a2[v >> 1]) : lo2(a2[v >> 1]);
        *(__half*)(arow + v*400) = __float2half(yv);
      }
    }
  }
  __syncthreads();

  // stage B(dv=0)->buf0, B(dv=1)->buf1 (sx no longer needed)
  for (int i = tid; i < 3200; i += 512) {
    int b = i >= 1600;
    ((uint4*)(smc + 51200))[i] = g_Wimg[b][i - b*1600];
  }
  __syncthreads();

  // Phase 2: D[m'][co] = sum_dv A[m'+dv][:] . B_dv[co][:]  (single fp16 term)
  // per (dv,kc): 3 ldmatrix.x4 + 4 mma.
  const int mband = wid >> 1, nhalf = wid & 1;
  const int r8 = lane & 7;
  const uint32_t aoff  = (uint32_t)((mband*16 + r8 + ((lane>>3)&1)*8)*400 + (lane>>4)*16);
  const uint32_t boff0 = (uint32_t)((nhalf*32 + r8 + ((lane>>4)&1)*8)*400 + ((lane>>3)&1)*16);

  float d[4][4];
  #pragma unroll
  for (int j = 0; j < 4; ++j)
    #pragma unroll
    for (int k = 0; k < 4; ++k) d[j][k] = 0.f;

  for (int dv = 0; dv < 5; ++dv) {
    const int b = dv & 1;
    const uint32_t abase = sbase + aoff + (uint32_t)dv*400u;
    const uint32_t bbase = sbase + 51200u + (uint32_t)b*25600u + boff0;
    #pragma unroll
    for (int kc = 0; kc < 12; ++kc) {
      uint32_t ah[4], b0[4], b1[4];
      ldm_x4(ah, abase + kc*32);
      ldm_x4(b0, bbase + kc*32);
      ldm_x4(b1, bbase + 6400 + kc*32);
      mma_f16(d[0], ah, b0);
      mma_f16(d[1], ah, b0 + 2);
      mma_f16(d[2], ah, b1);
      mma_f16(d[3], ah, b1 + 2);
    }
    if (dv < 3) {
      __syncthreads();
      for (int i = tid; i < 1600; i += 512)
        ((uint4*)(smc + 51200 + b*25600))[i] = g_Wimg[dv + 2][i];
      __syncthreads();
    }
  }

  // Epilogue: predicated direct stores with bias
  {
    const int g = lane >> 2;
    const int m0 = mband*16 + g;
    const int m1 = m0 + 8;
    const int t40 = m0 >> 5, v0 = m0 & 31;
    const int t41 = m1 >> 5, v1 = m1 & 31;
    const size_t zb = (size_t)n*204800;
    #pragma unroll
    for (int j = 0; j < 4; ++j) {
      int co = nhalf*32 + j*8 + (lane & 3)*2;
      float b0v = bout[co], b1v = bout[co + 1];
      if (v0 < 25) {
        size_t base = zb + (size_t)co*3200 + (t0 + t40)*25 + v0;
        g_z[base]        = d[j][0] + b0v;
        g_z[base + 3200] = d[j][1] + b1v;
      }
      if (v1 < 25) {
        size_t base = zb + (size_t)co*3200 + (t0 + t41)*25 + v1;
        g_z[base]        = d[j][2] + b0v;
        g_z[base + 3200] = d[j][3] + b1v;
      }
    }
  }
}

// ---------------- kernel C1: z stats (deterministic) ----------------
__global__ void k_zstat() {
  const int n = blockIdx.x;
  const int wid = threadIdx.x >> 5, lane = threadIdx.x & 31;   // 256 thr
  #pragma unroll
  for (int j = 0; j < 8; ++j) {
    int co = wid*8 + j;
    const float* zp = g_z + ((size_t)(n*C_ + co))*3200;
    float s = 0.f, q = 0.f;
    for (int i = lane; i < 3200; i += 32) { float v = zp[i]; s += v; q += v*v; }
    #pragma unroll
    for (int dd = 16; dd > 0; dd >>= 1) {
      s += __shfl_down_sync(0xffffffffu, s, dd);
      q += __shfl_down_sync(0xffffffffu, q, dd);
    }
    if (lane == 0) { g_bnpart[n*128 + co] = s; g_bnpart[n*128 + 64 + co] = q; }
  }
}

// ---------------- kernel C2: BN reduce ----------------
__global__ void k_bnred(const float* __restrict__ gamma, const float* __restrict__ beta) {
  __shared__ float tot[128];
  const int tid = threadIdx.x;   // 128
  float s = 0.f;
  for (int b = 0; b < 64; ++b) s += g_bnpart[b*128 + tid];
  tot[tid] = s;
  __syncthreads();
  if (tid < 64) {
    const float inv = 1.0f / 204800.0f;
    float mean = tot[tid] * inv;
    float var  = tot[64 + tid] * inv - mean*mean;
    float a = gamma[tid] * rsqrtf(var + 1e-5f);
    g_bn[tid]      = a;
    g_bn[64 + tid] = beta[tid] - mean * a;
  }
}

// ---------------- kernel D: epilogue ----------------
__global__ void k_out(const float* __restrict__ x, float* __restrict__ out) {
  const float4* z4 = (const float4*)g_z;
  const float4* x4 = (const float4*)x;
  float4* o4 = (float4*)out;
  const int total = (N_*C_*T_*V_) / 4;
  for (int i = blockIdx.x*blockDim.x + threadIdx.x; i < total; i += gridDim.x*blockDim.x) {
    int c = (i / 800) & 63;
    float a = g_bn[c], b = g_bn[64 + c];
    float4 z = z4[i], xx = x4[i], r;
    float v;
    v = z.x*a + b + xx.x; r.x = fmaxf(v, 0.1f*v);
    v = z.y*a + b + xx.y; r.y = fmaxf(v, 0.1f*v);
    v = z.z*a + b + xx.z; r.z = fmaxf(v, 0.1f*v);
    v = z.w*a + b + xx.w; r.w = fmaxf(v, 0.1f*v);
    o4[i] = r;
  }
}

// ---------------- launch ----------------
extern "C" void kernel_launch(void* const* d_in, const int* in_sizes, int n_in,
                              void* d_out, int out_size) {
  const float* x      = (const float*)d_in[0];
  const float* Wqkv   = (const float*)d_in[1];
  const float* bqkv   = (const float*)d_in[2];
  const float* alphas = (const float*)d_in[3];
  const float* att0s  = (const float*)d_in[4];
  const float* Wout   = (const float*)d_in[5];
  const float* bout   = (const float*)d_in[6];
  const float* gamma  = (const float*)d_in[7];
  const float* beta   = (const float*)d_in[8];
  float* out = (float*)d_out;

  cudaFuncSetAttribute(k_qkatt, cudaFuncAttributeMaxDynamicSharedMemorySize, 168960);
  cudaFuncSetAttribute(k_main,  cudaFuncAttributeMaxDynamicSharedMemorySize, 110800);

  k_init<<<64, 256>>>(Wqkv, Wout);
  k_qkatt<<<dim3(8, 64), 384, 168960>>>(x, bqkv);
  k_att2<<<(N_*1875 + 255)/256, 256>>>(alphas, att0s);
  k_main<<<dim3(32, 64), 512, 110800>>>(x, bout);
  k_zstat<<<64, 256>>>();
  k_bnred<<<1, 128>>>(gamma, beta);
  k_out<<<4096, 256>>>(x, out);
}

// round 13
// speedup vs baseline: 2.7392x; 1.0409x over previous
#include <cuda_runtime.h>
#include <cuda_bf16.h>
#include <cuda_fp16.h>
#include <cstdint>

#define N_  64
#define C_  64
#define T_  128
#define V_  25
#define H_  3
#define O_  192

typedef unsigned long long ull;

// ---------------- scratch ----------------
__device__ __align__(16) float g_pe[C_*V_];
__device__ __align__(16) float g_attpart[64*8*300*26];
__device__ __align__(16) float g_att[N_*H_*V_*V_];
__device__ __align__(16) float g_z[N_*C_*T_*V_];
__device__ __align__(16) float g_bnpart[2048*128];
__device__ __align__(16) float g_bn[128];
// conv W per dv: [co=64][colp=200] fp16 = 25600 B = 1600 uint4
__device__ __align__(16) uint4 g_Wimg[5][1600];
// QKV W image: [term hi/lo][o=192][c=72pad] fp16 = 55296 B = 3456 uint4
__device__ __align__(16) uint4 g_WqkvImg[3456];

// ---------------- f32x2 helpers ----------------
static __device__ __forceinline__ ull pack2(float a, float b){
  ull r; asm("mov.b64 %0, {%1, %2};" : "=l"(r) : "f"(a), "f"(b)); return r;
}
static __device__ __forceinline__ void fma2(ull& d, ull a, ull b){
  asm("fma.rn.f32x2 %0, %1, %2, %0;" : "+l"(d) : "l"(a), "l"(b));
}
static __device__ __forceinline__ float lo2(ull v){ return __uint_as_float((unsigned)v); }
static __device__ __forceinline__ float hi2(ull v){ return __uint_as_float((unsigned)(v>>32)); }

// ---------------- portable tensor-core helpers (sm_80+ baseline PTX) ----------------
static __device__ __forceinline__ uint32_t smem_to_u32(const void* p) {
  uint32_t a;
  asm("{ .reg .u64 t; cvta.to.shared.u64 t, %1; cvt.u32.u64 %0, t; }" : "=r"(a) : "l"(p));
  return a;
}
static __device__ __forceinline__ void ldm_x4(uint32_t* r, uint32_t addr){
  asm volatile("ldmatrix.sync.aligned.m8n8.x4.shared.b16 {%0,%1,%2,%3}, [%4];"
    : "=r"(r[0]), "=r"(r[1]), "=r"(r[2]), "=r"(r[3]) : "r"(addr));
}
static __device__ __forceinline__ void mma_f16(float* d, const uint32_t* a, const uint32_t* b){
  asm volatile("mma.sync.aligned.m16n8k16.row.col.f32.f16.f16.f32 "
    "{%0,%1,%2,%3}, {%4,%5,%6,%7}, {%8,%9}, {%0,%1,%2,%3};"
    : "+f"(d[0]), "+f"(d[1]), "+f"(d[2]), "+f"(d[3])
    : "r"(a[0]), "r"(a[1]), "r"(a[2]), "r"(a[3]), "r"(b[0]), "r"(b[1]));
}

// ---------------- init ----------------
__global__ void k_init(const float* __restrict__ Wqkv, const float* __restrict__ Wout) {
  const int stride = gridDim.x * blockDim.x;
  const int i0 = blockIdx.x * blockDim.x + threadIdx.x;
  for (int i = i0; i < C_*V_; i += stride) {
    int c = i / V_, v = i - (i / V_) * V_;
    int ii = c >> 1;
    float dv = __expf(-(2.0f * ii) * (logf(10000.0f) / 64.0f));
    float ang = (float)v * dv;
    g_pe[i] = (c & 1) ? cosf(ang) : sinf(ang);
  }
  {
    __half* wb = (__half*)g_WqkvImg;
    for (int i = i0; i < 2*192*72; i += stride) {
      int term = i / 13824; int r = i - term*13824;
      int o = r / 72, c = r - (r/72)*72;
      float w = (c < 64) ? Wqkv[o*64 + c] : 0.f;
      __half hb = __float2half(w);
      wb[i] = (term == 0) ? hb : __float2half(w - __half2float(hb));
    }
  }
  {
    __half* wb = (__half*)g_Wimg;
    for (int i = i0; i < 5*64*200; i += stride) {
      int dv = i / 12800; int r = i - dv*12800;
      int co = r / 200; int cp = r - co*200;
      float w = (cp < 192) ? Wout[co*960 + cp*5 + dv] : 0.f;
      wb[i] = __float2half(w);
    }
  }
}

// ---------------- kernel A: QK GEMM (mma.sync fp16 3-term) + scalar Gram ----------------
// staging index remap: i bits -> c = b0-2 | b5-7<<3, r = b3-4 | (i>>8)*4
// => per warp: 8 consecutive c x 4 consecutive r => conflict-free 2B STS.
#define QKP 106
__global__ __launch_bounds__(384, 1) void k_qkatt(const float* __restrict__ x,
                                                  const float* __restrict__ bqkv) {
  extern __shared__ char sqc[];
  const uint32_t sbase = smem_to_u32(sqc);
  float* qk = (float*)(sqc + 87552);
  const int tid = threadIdx.x;
  const int wid = tid >> 5, lane = tid & 31;
  const int n = blockIdx.y, tc = blockIdx.x;
  const int t0 = tc * 16;

  for (int i = tid; i < 3456; i += 384) ((uint4*)sqc)[i] = g_WqkvImg[i];

  {
    const float* xg = x + (((size_t)n*C_)*T_ + t0)*V_;
    for (int i = tid; i < 6400; i += 384) {
      int c = (i & 7) | (((i >> 5) & 7) << 3);
      int r = ((i >> 3) & 3) | ((i >> 8) << 2);
      int tl = r / 25, v = r - tl*25;
      float xv = xg[(size_t)c*3200 + r] + g_pe[c*25 + v];
      int boff = (tl*26 + v)*144 + c*2;
      __half hb = __float2half(xv);
      *(__half*)(sqc + 55296 + boff) = hb;
      *(__half*)(sqc + 71424 + boff) = __float2half(xv - __half2float(hb));
    }
  }
  __syncthreads();

  const int m0 = wid * 16;
  const uint32_t aoff = (uint32_t)((m0 + (lane&7) + ((lane>>3)&1)*8)*144 + (lane>>4)*16);
  uint32_t ah[4][4], al[4][4];
  #pragma unroll
  for (int kc = 0; kc < 4; ++kc) {
    ldm_x4(ah[kc], sbase + aoff + kc*32);
    ldm_x4(al[kc], sbase + 27648u + aoff + kc*32);
  }
  const int g = lane >> 2, c0 = (lane&3)*2;
  const float bq0 = bqkv[m0 + g];
  const float bq1 = bqkv[m0 + g + 8];

  const int grow = tid >> 2, gcq = tid & 3;
  const bool gact = (tid < 300);
  const int gh = grow / 25, gu = grow - (grow/25)*25;
  ull gacc[13];
  #pragma unroll
  for (int j = 0; j < 13; ++j) gacc[j] = 0ULL;

  const uint32_t bboff = (uint32_t)(((lane&7) + ((lane>>4)&1)*8)*144 + ((lane>>3)&1)*16);

  for (int ck = 0; ck < 4; ++ck) {
    float d[14][4];
    #pragma unroll
    for (int nt = 0; nt < 14; ++nt)
      #pragma unroll
      for (int j = 0; j < 4; ++j) d[nt][j] = 0.f;

    #pragma unroll
    for (int p = 0; p < 7; ++p) {
      const uint32_t bb = sbase + 55296u + (uint32_t)p*2304u + bboff;
      #pragma unroll
      for (int kc = 0; kc < 4; ++kc) {
        uint32_t bh[4], bl[4];
        ldm_x4(bh, bb + kc*32);
        ldm_x4(bl, bb + 16128u + kc*32);
        mma_f16(d[2*p],   ah[kc], bh);
        mma_f16(d[2*p+1], ah[kc], bh + 2);
        mma_f16(d[2*p],   ah[kc], bl);
        mma_f16(d[2*p+1], ah[kc], bl + 2);
        mma_f16(d[2*p],   al[kc], bh);
        mma_f16(d[2*p+1], al[kc], bh + 2);
      }
    }
    #pragma unroll
    for (int nt = 0; nt < 13; ++nt) {
      int col = nt*8 + c0;
      float* r0 = qk + (m0 + g)*QKP + col;
      float* r1 = qk + (m0 + g + 8)*QKP + col;
      r0[0] = d[nt][0] + bq0; r0[1] = d[nt][1] + bq0;
      r1[0] = d[nt][2] + bq1; r1[1] = d[nt][3] + bq1;
    }
    __syncthreads();

    if (gact) {
      #pragma unroll
      for (int tl = 0; tl < 4; ++tl) {
        #pragma unroll
        for (int c8 = 0; c8 < 8; ++c8) {
          int c = gcq*8 + c8;
          float qv = qk[(gh*32 + c)*QKP + tl*26 + gu];
          ull q2 = pack2(qv, qv);
          const ull* kp = (const ull*)(qk + (96 + gh*32 + c)*QKP) + tl*13;
          #pragma unroll
          for (int j = 0; j < 13; ++j) fma2(gacc[j], q2, kp[j]);
        }
      }
    }
    if (ck < 3) {
      const float* xg = x + (((size_t)n*C_)*T_ + t0 + (ck+1)*4)*V_;
      for (int i = tid; i < 6400; i += 384) {
        int c = (i & 7) | (((i >> 5) & 7) << 3);
        int r = ((i >> 3) & 3) | ((i >> 8) << 2);
        int tl = r / 25, v = r - tl*25;
        float xv = xg[(size_t)c*3200 + r] + g_pe[c*25 + v];
        int boff = (tl*26 + v)*144 + c*2;
        __half hb = __float2half(xv);
        *(__half*)(sqc + 55296 + boff) = hb;
        *(__half*)(sqc + 71424 + boff) = __float2half(xv - __half2float(hb));
      }
    }
    __syncthreads();
  }

  if (gact) {
    ull* op = (ull*)(g_attpart + ((size_t)(n*8 + tc)*300 + tid)*26);
    #pragma unroll
    for (int j = 0; j < 13; ++j) op[j] = gacc[j];
  }
}

// ---------------- kernel A2 ----------------
__global__ void k_att2(const float* __restrict__ alphas, const float* __restrict__ att0s) {
  int i = blockIdx.x * blockDim.x + threadIdx.x;
  if (i >= N_*1875) return;
  int n = i / 1875, r = i - n*1875;
  int h = r / 625, rr = r - h*625;
  int u = rr / 25, v = rr - (rr/25)*25;
  int row = h*25 + u;
  float s = 0.f;
  #pragma unroll
  for (int tc = 0; tc < 8; ++tc)
    #pragma unroll
    for (int cq = 0; cq < 4; ++cq)
      s += g_attpart[((size_t)(n*8 + tc)*300 + row*4 + cq)*26 + v];
  g_att[i] = tanhf(s * (1.0f/4096.0f)) * alphas[h] + att0s[r];
}

// ---------------- kernel B: att-apply (FFMA2) + conv (mma.sync fp16) + BN partials ----------------
// grid (32 tc, 64 n), 512 threads, 2 CTAs/SM. smem total 110800 B.
__global__ __launch_bounds__(512, 2) void k_main(const float* __restrict__ x,
                                                 const float* __restrict__ bout) {
  extern __shared__ char smc[];
  const uint32_t sbase = smem_to_u32(smc);
  float* satt = (float*)(smc + 102400);
  float* sx   = (float*)(smc + 51200);

  const int tid = threadIdx.x;
  const int wid = tid >> 5, lane = tid & 31;
  const int n = blockIdx.y;
  const int t0 = blockIdx.x * 4;

  for (int i = tid; i < 3200; i += 512) ((uint4*)smc)[i] = make_uint4(0,0,0,0);

  for (int i = tid; i < 1875; i += 512) {
    int h = i / 625, r = i - h*625;
    int u = r / 25, v = r - (r/25)*25;
    satt[(h*25 + u)*28 + v] = g_att[(size_t)n*1875 + i];
  }
  for (int i = tid; i < 225; i += 512) { int row = i/3, c = 25 + (i - (i/3)*3); satt[row*28 + c] = 0.f; }

  {
    const float* xg = x + (((size_t)n*C_)*T_ + t0)*V_;
    for (int i = tid; i < 6400; i += 512) {
      int ci = i / 100, r = i - ci*100;
      sx[ci*101 + r] = xg[(size_t)ci*3200 + r];
    }
  }
  __syncthreads();

  // Phase 1: y[ch][t4][v] -> A[t4*32 + v + 2][ch] as fp16
  #pragma unroll
  for (int rep = 0; rep < 2; ++rep) {
    int task = tid + 512*rep;
    if (task < 768) {
      int h = task >> 8, t4 = (task >> 6) & 3, ci = task & 63;
      ull a2[13];
      #pragma unroll
      for (int j = 0; j < 13; ++j) a2[j] = 0ULL;
      const float* sxp = sx + ci*101 + t4*25;
      const float* ap0 = satt + h*25*28;
      #pragma unroll
      for (int u = 0; u < 25; ++u) {
        float xv = sxp[u];
        ull xp = pack2(xv, xv);
        const ull* ar = (const ull*)(ap0 + u*28);
        #pragma unroll
        for (int j = 0; j < 13; ++j) fma2(a2[j], xp, ar[j]);
      }
      const int ch = h*64 + ci;
      char* arow = smc + (t4*32 + 2)*400 + ch*2;
      #pragma unroll
      for (int v = 0; v < 25; ++v) {
        float yv = (v & 1) ? hi2(a2[v >> 1]) : lo2(a2[v >> 1]);
        *(__half*)(arow + v*400) = __float2half(yv);
      }
    }
  }
  __syncthreads();

  for (int i = tid; i < 3200; i += 512) {
    int b = i >= 1600;
    ((uint4*)(smc + 51200))[i] = g_Wimg[b][i - b*1600];
  }
  __syncthreads();

  // Phase 2: conv GEMM (single fp16 term)
  const int mband = wid >> 1, nhalf = wid & 1;
  const int r8 = lane & 7;
  const uint32_t aoff  = (uint32_t)((mband*16 + r8 + ((lane>>3)&1)*8)*400 + (lane>>4)*16);
  const uint32_t boff0 = (uint32_t)((nhalf*32 + r8 + ((lane>>4)&1)*8)*400 + ((lane>>3)&1)*16);

  float d[4][4];
  #pragma unroll
  for (int j = 0; j < 4; ++j)
    #pragma unroll
    for (int k = 0; k < 4; ++k) d[j][k] = 0.f;

  for (int dv = 0; dv < 5; ++dv) {
    const int b = dv & 1;
    const uint32_t abase = sbase + aoff + (uint32_t)dv*400u;
    const uint32_t bbase = sbase + 51200u + (uint32_t)b*25600u + boff0;
    #pragma unroll
    for (int kc = 0; kc < 12; ++kc) {
      uint32_t ah[4], b0[4], b1[4];
      ldm_x4(ah, abase + kc*32);
      ldm_x4(b0, bbase + kc*32);
      ldm_x4(b1, bbase + 6400 + kc*32);
      mma_f16(d[0], ah, b0);
      mma_f16(d[1], ah, b0 + 2);
      mma_f16(d[2], ah, b1);
      mma_f16(d[3], ah, b1 + 2);
    }
    if (dv < 3) {
      __syncthreads();
      for (int i = tid; i < 1600; i += 512)
        ((uint4*)(smc + 51200 + b*25600))[i] = g_Wimg[dv + 2][i];
      __syncthreads();
    }
  }

  // Epilogue: predicated direct stores with bias + BN partial sums
  float bs[8], bq[8];
  {
    const int g = lane >> 2;
    const int m0 = mband*16 + g;
    const int m1 = m0 + 8;
    const int t40 = m0 >> 5, v0 = m0 & 31;
    const int t41 = m1 >> 5, v1 = m1 & 31;
    const size_t zb = (size_t)n*204800;
    #pragma unroll
    for (int j = 0; j < 4; ++j) {
      int co = nhalf*32 + j*8 + (lane & 3)*2;
      float b0v = bout[co], b1v = bout[co + 1];
      float s0 = 0.f, q0 = 0.f, s1 = 0.f, q1 = 0.f;
      if (v0 < 25) {
        size_t base = zb + (size_t)co*3200 + (t0 + t40)*25 + v0;
        float z0 = d[j][0] + b0v, z1 = d[j][1] + b1v;
        g_z[base]        = z0;
        g_z[base + 3200] = z1;
        s0 += z0; q0 += z0*z0; s1 += z1; q1 += z1*z1;
      }
      if (v1 < 25) {
        size_t base = zb + (size_t)co*3200 + (t0 + t41)*25 + v1;
        float z2 = d[j][2] + b0v, z3 = d[j][3] + b1v;
        g_z[base]        = z2;
        g_z[base + 3200] = z3;
        s0 += z2; q0 += z2*z2; s1 += z3; q1 += z3*z3;
      }
      bs[2*j] = s0; bq[2*j] = q0; bs[2*j+1] = s1; bq[2*j+1] = q1;
    }
  }
  // reduce over g-lanes (stride 4, 8, 16)
  #pragma unroll
  for (int off = 4; off <= 16; off <<= 1) {
    #pragma unroll
    for (int k = 0; k < 8; ++k) {
      bs[k] += __shfl_xor_sync(0xffffffffu, bs[k], off);
      bq[k] += __shfl_xor_sync(0xffffffffu, bq[k], off);
    }
  }
  __syncthreads();   // A/B smem regions now free
  float* sred  = (float*)smc;            // [16][64] sum
  float* sred2 = (float*)(smc + 4096);   // [16][64] sumsq
  if ((lane >> 2) == 0) {
    #pragma unroll
    for (int j = 0; j < 4; ++j) {
      int col = nhalf*32 + j*8 + (lane & 3)*2;
      sred[wid*64 + col]      = bs[2*j];
      sred[wid*64 + col + 1]  = bs[2*j+1];
      sred2[wid*64 + col]     = bq[2*j];
      sred2[wid*64 + col + 1] = bq[2*j+1];
    }
  }
  __syncthreads();
  {
    const int cta = blockIdx.y*32 + blockIdx.x;
    if (tid < 64) {
      float s = 0.f;
      #pragma unroll
      for (int r = 0; r < 16; ++r) s += sred[r*64 + tid];
      g_bnpart[(size_t)cta*128 + tid] = s;
    } else if (tid < 128) {
      float s = 0.f;
      #pragma unroll
      for (int r = 0; r < 16; ++r) s += sred2[r*64 + tid - 64];
      g_bnpart[(size_t)cta*128 + tid] = s;
    }
  }
}

// ---------------- kernel C: BN reduce (2048 CTA partials) ----------------
__global__ void k_bnred(const float* __restrict__ gamma, const float* __restrict__ beta) {
  __shared__ float s[4][128];
  __shared__ float tot[128];
  const int tid = threadIdx.x;           // 512
  const int slot = tid & 127, part = tid >> 7;
  float sum = 0.f;
  for (int b = part; b < 2048; b += 4) sum += g_bnpart[(size_t)b*128 + slot];
  s[part][slot] = sum;
  __syncthreads();
  if (tid < 128) tot[tid] = s[0][tid] + s[1][tid] + s[2][tid] + s[3][tid];
  __syncthreads();
  if (tid < 64) {
    const float inv = 1.0f / 204800.0f;
    float mean = tot[tid] * inv;
    float var  = tot[64 + tid] * inv - mean*mean;
    float a = gamma[tid] * rsqrtf(var + 1e-5f);
    g_bn[tid]      = a;
    g_bn[64 + tid] = beta[tid] - mean * a;
  }
}

// ---------------- kernel D: epilogue ----------------
__global__ void k_out(const float* __restrict__ x, float* __restrict__ out) {
  const float4* z4 = (const float4*)g_z;
  const float4* x4 = (const float4*)x;
  float4* o4 = (float4*)out;
  const int total = (N_*C_*T_*V_) / 4;
  for (int i = blockIdx.x*blockDim.x + threadIdx.x; i < total; i += gridDim.x*blockDim.x) {
    int c = (i / 800) & 63;
    float a = g_bn[c], b = g_bn[64 + c];
    float4 z = z4[i], xx = x4[i], r;
    float v;
    v = z.x*a + b + xx.x; r.x = fmaxf(v, 0.1f*v);
    v = z.y*a + b + xx.y; r.y = fmaxf(v, 0.1f*v);
    v = z.z*a + b + xx.z; r.z = fmaxf(v, 0.1f*v);
    v = z.w*a + b + xx.w; r.w = fmaxf(v, 0.1f*v);
    o4[i] = r;
  }
}

// ---------------- launch ----------------
extern "C" void kernel_launch(void* const* d_in, const int* in_sizes, int n_in,
                              void* d_out, int out_size) {
  const float* x      = (const float*)d_in[0];
  const float* Wqkv   = (const float*)d_in[1];
  const float* bqkv   = (const float*)d_in[2];
  const float* alphas = (const float*)d_in[3];
  const float* att0s  = (const float*)d_in[4];
  const float* Wout   = (const float*)d_in[5];
  const float* bout   = (const float*)d_in[6];
  const float* gamma  = (const float*)d_in[7];
  const float* beta   = (const float*)d_in[8];
  float* out = (float*)d_out;

  cudaFuncSetAttribute(k_qkatt, cudaFuncAttributeMaxDynamicSharedMemorySize, 168960);
  cudaFuncSetAttribute(k_main,  cudaFuncAttributeMaxDynamicSharedMemorySize, 110800);

  k_init<<<64, 256>>>(Wqkv, Wout);
  k_qkatt<<<dim3(8, 64), 384, 168960>>>(x, bqkv);
  k_att2<<<(N_*1875 + 255)/256, 256>>>(alphas, att0s);
  k_main<<<dim3(32, 64), 512, 110800>>>(x, bout);
  k_bnred<<<1, 512>>>(gamma, beta);
  k_out<<<4096, 256>>>(x, out);
}